// round 12
// baseline (speedup 1.0000x reference)
#include <cuda_runtime.h>
#include <cuda_fp16.h>
#include <cstdint>
#include <math.h>

#define LSEQ   2048
#define DMODEL 1024
#define NHEAD  16
#define HDIM   64

// ---------------------------------------------------------------------------
// Scratch (__device__ globals; allocation-free rule). All fp16.
// ---------------------------------------------------------------------------
__device__ __align__(16) __half g_xh[3][LSEQ * DMODEL];   // activations hi
__device__ __align__(16) __half g_xl[3][LSEQ * DMODEL];   // activations lo
__device__ __align__(16) __half g_wh[4][DMODEL * DMODEL]; // weights single fp16, [n][k]
__device__ __align__(16) __half g_qh[LSEQ * DMODEL];      // Q hi (unscaled)
__device__ __align__(16) __half g_ql[LSEQ * DMODEL];      // Q lo
__device__ __align__(16) __half g_kh[LSEQ * DMODEL];      // K single, pre-scaled by 0.125*log2e
__device__ __align__(16) __half g_vh[LSEQ * DMODEL];      // V single
__device__ __align__(16) __half g_ah[LSEQ * DMODEL];      // attention out hi
__device__ __align__(16) __half g_al[LSEQ * DMODEL];      // attention out lo

// ---------------------------------------------------------------------------
// Base-ISA tensor-core + async-copy helpers
// ---------------------------------------------------------------------------
__device__ __forceinline__ uint32_t smem_u32(const void* p) {
    uint32_t a;
    asm("{ .reg .u64 t; cvta.to.shared.u64 t, %1; cvt.u32.u64 %0, t; }" : "=r"(a) : "l"(p));
    return a;
}
__device__ __forceinline__ void ldsm_x4(uint32_t* r, uint32_t addr) {
    asm volatile("ldmatrix.sync.aligned.m8n8.x4.shared.b16 {%0,%1,%2,%3}, [%4];"
                 : "=r"(r[0]), "=r"(r[1]), "=r"(r[2]), "=r"(r[3]) : "r"(addr));
}
__device__ __forceinline__ void ldsm_x4_t(uint32_t* r, uint32_t addr) {
    asm volatile("ldmatrix.sync.aligned.m8n8.x4.trans.shared.b16 {%0,%1,%2,%3}, [%4];"
                 : "=r"(r[0]), "=r"(r[1]), "=r"(r[2]), "=r"(r[3]) : "r"(addr));
}
__device__ __forceinline__ void mma_h(float* c, const uint32_t* a, const uint32_t* b) {
    asm volatile(
        "mma.sync.aligned.m16n8k16.row.col.f32.f16.f16.f32 "
        "{%0,%1,%2,%3}, {%4,%5,%6,%7}, {%8,%9}, {%0,%1,%2,%3};"
        : "+f"(c[0]), "+f"(c[1]), "+f"(c[2]), "+f"(c[3])
        : "r"(a[0]), "r"(a[1]), "r"(a[2]), "r"(a[3]), "r"(b[0]), "r"(b[1]));
}
__device__ __forceinline__ void cp16(uint32_t dst, const void* src) {
    asm volatile("cp.async.cg.shared.global [%0], [%1], 16;" :: "r"(dst), "l"(src));
}
#define CP_COMMIT() asm volatile("cp.async.commit_group;" ::: "memory")
#define CP_WAIT0()  asm volatile("cp.async.wait_group 0;" ::: "memory")
#define CP_WAIT1()  asm volatile("cp.async.wait_group 1;" ::: "memory")

__device__ __forceinline__ float ex2(float x) {
    float y;
    asm("ex2.approx.f32 %0, %1;" : "=f"(y) : "f"(x));
    return y;
}

// ---------------------------------------------------------------------------
// fp16 split helpers
// ---------------------------------------------------------------------------
__device__ __forceinline__ void split_h(float x, __half& h, __half& l) {
    h = __float2half_rn(x);
    l = __float2half_rn(x - __half2float(h));
}
__device__ __forceinline__ void pack_pair_h(float a, float b, uint32_t& hi, uint32_t& lo) {
    __half2 h = __floats2half2_rn(a, b);
    float ra = a - __half2float(__low2half(h));
    float rb = b - __half2float(__high2half(h));
    __half2 l = __floats2half2_rn(ra, rb);
    hi = *reinterpret_cast<uint32_t*>(&h);
    lo = *reinterpret_cast<uint32_t*>(&l);
}
__device__ __forceinline__ uint32_t pack_single_h(float a, float b) {
    __half2 h = __floats2half2_rn(a, b);
    return *reinterpret_cast<uint32_t*>(&h);
}

// Elementwise split of activations (q,k,v inputs), z-batched
__global__ void conv_x_kernel(const float* __restrict__ q, const float* __restrict__ k,
                              const float* __restrict__ v) {
    int z = blockIdx.z;
    const float* src = (z == 0) ? q : (z == 1) ? k : v;
    __half* hi = g_xh[z];
    __half* lo = g_xl[z];
    int i = (blockIdx.x * 256 + threadIdx.x) * 4;
    float4 xv = *(const float4*)(src + i);
    union { __half b[4]; uint2 u; } H, L;
    split_h(xv.x, H.b[0], L.b[0]);
    split_h(xv.y, H.b[1], L.b[1]);
    split_h(xv.z, H.b[2], L.b[2]);
    split_h(xv.w, H.b[3], L.b[3]);
    *(uint2*)(hi + i) = H.u;
    *(uint2*)(lo + i) = L.u;
}

// Transpose weights to [n][k] single fp16, z-batched over 4.
__global__ void conv_w_kernel(const float* __restrict__ wq, const float* __restrict__ wk,
                              const float* __restrict__ wv, const float* __restrict__ wo) {
    __shared__ float tile[32][33];
    int z = blockIdx.z;
    const float* W = (z == 0) ? wq : (z == 1) ? wk : (z == 2) ? wv : wo;
    __half* Th = g_wh[z];

    int n0 = blockIdx.x * 32;
    int k0 = blockIdx.y * 32;
    int tx = threadIdx.x, ty = threadIdx.y;
#pragma unroll
    for (int i = 0; i < 4; i++)
        tile[ty + i * 8][tx] = W[(size_t)(k0 + ty + i * 8) * DMODEL + n0 + tx];
    __syncthreads();
#pragma unroll
    for (int i = 0; i < 4; i++) {
        float val = tile[tx][ty + i * 8];
        Th[(size_t)(n0 + ty + i * 8) * DMODEL + k0 + tx] = __float2half_rn(val);
    }
}

// ---------------------------------------------------------------------------
// HMMA GEMM, 2-pass fp16 (A split, B single), 3-stage cp.async ring.
// C = A @ Wt^T + bias; CTA 128x128, BK=64, 256 threads.
// ---------------------------------------------------------------------------
#define GSTRIDE 144                     // bytes per smem row: 64 fp16 + pad
#define GTILE   (128 * GSTRIDE)         // 18432 B
#define OF_AH   0
#define OF_AL   (1 * GTILE)
#define OF_BH   (2 * GTILE)
#define GBUF    (3 * GTILE)             // 55296 B per stage
#define GEMM_SMEM (3 * GBUF)            // 165888 B

extern __shared__ char smraw[];

__device__ __forceinline__ void issue_tile(uint32_t dst, const __half* __restrict__ src,
                                           int row0, int k0, int tid) {
#pragma unroll
    for (int i = 0; i < 4; i++) {
        int idx = tid + i * 256;
        int row = idx >> 3;
        int c16 = idx & 7;
        cp16(dst + row * GSTRIDE + c16 * 16,
             src + (size_t)(row0 + row) * DMODEL + k0 + c16 * 8);
    }
}

__device__ __forceinline__ void issue_stage(uint32_t buf,
                                            const __half* Ah, const __half* Al,
                                            const __half* Bh,
                                            int bm, int bn, int k0, int tid) {
    issue_tile(buf + OF_AH, Ah, bm, k0, tid);
    issue_tile(buf + OF_AL, Al, bm, k0, tid);
    issue_tile(buf + OF_BH, Bh, bn, k0, tid);
    CP_COMMIT();
}

// MODE: 0 = fp32 out, 1 = split fp16 out (hi/lo), 2 = single fp16 out (scaled)
__device__ __forceinline__ void gemm_mma_body(
    const __half* __restrict__ Ah, const __half* __restrict__ Al,
    const __half* __restrict__ Bh,
    const float* __restrict__ bias, float oscale, int mode,
    float* __restrict__ C, __half* __restrict__ Chi, __half* __restrict__ Clo)
{
    const uint32_t smb = smem_u32(smraw);
    const int tid  = threadIdx.x;
    const int lane = tid & 31;
    const int wid  = tid >> 5;
    const int wm   = wid >> 2;
    const int wn   = wid & 3;
    const int bm   = blockIdx.y * 128;
    const int bn   = blockIdx.x * 128;
    const int NCH  = DMODEL / 64;

    float acc[4][4][4];
#pragma unroll
    for (int mi = 0; mi < 4; mi++)
#pragma unroll
        for (int ni = 0; ni < 4; ni++)
#pragma unroll
            for (int c = 0; c < 4; c++) acc[mi][ni][c] = 0.0f;

    const uint32_t aBase = (uint32_t)(wm * 64 + (lane & 15)) * GSTRIDE + ((lane >> 4) << 4);
    const uint32_t bBase = (uint32_t)(wn * 32 + (lane & 7) + ((lane >> 4) << 3)) * GSTRIDE
                         + (((lane >> 3) & 1) << 4);

    issue_stage(smb + 0 * GBUF, Ah, Al, Bh, bm, bn, 0, tid);
    issue_stage(smb + 1 * GBUF, Ah, Al, Bh, bm, bn, 64, tid);

    int cbi = 0;
    for (int chunk = 0; chunk < NCH; chunk++) {
        if (chunk < NCH - 1) CP_WAIT1(); else CP_WAIT0();
        __syncthreads();
        if (chunk + 2 < NCH) {
            int nbi = cbi + 2; if (nbi >= 3) nbi -= 3;
            issue_stage(smb + nbi * GBUF, Ah, Al, Bh, bm, bn, (chunk + 2) * 64, tid);
        }
        const uint32_t cb = smb + cbi * GBUF;

#pragma unroll
        for (int kk = 0; kk < 4; kk++) {
            const uint32_t kOff = kk * 32;
            uint32_t ah[4][4], al[4][4], bh[2][4];
#pragma unroll
            for (int mi = 0; mi < 4; mi++) {
                ldsm_x4(ah[mi], cb + OF_AH + aBase + mi * (16 * GSTRIDE) + kOff);
                ldsm_x4(al[mi], cb + OF_AL + aBase + mi * (16 * GSTRIDE) + kOff);
            }
#pragma unroll
            for (int nj = 0; nj < 2; nj++)
                ldsm_x4(bh[nj], cb + OF_BH + bBase + nj * (16 * GSTRIDE) + kOff);
            // 2 passes: Ah*Bh, Al*Bh (acc reuse distance 16)
#pragma unroll
            for (int mi = 0; mi < 4; mi++)
#pragma unroll
                for (int ni = 0; ni < 4; ni++)
                    mma_h(acc[mi][ni], ah[mi], &bh[ni >> 1][(ni & 1) * 2]);
#pragma unroll
            for (int mi = 0; mi < 4; mi++)
#pragma unroll
                for (int ni = 0; ni < 4; ni++)
                    mma_h(acc[mi][ni], al[mi], &bh[ni >> 1][(ni & 1) * 2]);
        }
        if (++cbi >= 3) cbi -= 3;
    }

    const int g = lane >> 2;
    const int t = lane & 3;
#pragma unroll
    for (int mi = 0; mi < 4; mi++) {
        const int row = bm + wm * 64 + mi * 16 + g;
#pragma unroll
        for (int ni = 0; ni < 4; ni++) {
            const int col = bn + wn * 32 + ni * 8 + t * 2;
            const float b0 = bias[col], b1 = bias[col + 1];
            float v0 = acc[mi][ni][0] + b0, v1 = acc[mi][ni][1] + b1;
            float v2 = acc[mi][ni][2] + b0, v3 = acc[mi][ni][3] + b1;
            const size_t o0 = (size_t)row * DMODEL + col;
            const size_t o1 = (size_t)(row + 8) * DMODEL + col;
            if (mode == 0) {
                *(float2*)(C + o0) = make_float2(v0, v1);
                *(float2*)(C + o1) = make_float2(v2, v3);
            } else if (mode == 1) {
                uint32_t h0, l0, h1, l1;
                pack_pair_h(v0, v1, h0, l0);
                pack_pair_h(v2, v3, h1, l1);
                *(uint32_t*)(Chi + o0) = h0;
                *(uint32_t*)(Clo + o0) = l0;
                *(uint32_t*)(Chi + o1) = h1;
                *(uint32_t*)(Clo + o1) = l1;
            } else {
                *(uint32_t*)(Chi + o0) = pack_single_h(v0 * oscale, v1 * oscale);
                *(uint32_t*)(Chi + o1) = pack_single_h(v2 * oscale, v3 * oscale);
            }
        }
    }
}

// softmax scale * log2(e), folded into K (single-rounded operand)
#define QSCALE (0.125f * 1.44269504088896340736f)

__global__ __launch_bounds__(256) void qkv_mma_kernel(
    const float* __restrict__ bq, const float* __restrict__ bk, const float* __restrict__ bv)
{
    int z = blockIdx.z;
    if (z == 0) {
        // Q: split fp16, unscaled (residuals stay in fp16-normal range)
        gemm_mma_body(g_xh[0], g_xl[0], g_wh[0], bq, 1.0f, 1, nullptr, g_qh, g_ql);
    } else if (z == 1) {
        // K: single fp16, pre-scaled by QSCALE
        gemm_mma_body(g_xh[1], g_xl[1], g_wh[1], bk, QSCALE, 2, nullptr, g_kh, nullptr);
    } else {
        // V: single fp16
        gemm_mma_body(g_xh[2], g_xl[2], g_wh[2], bv, 1.0f, 2, nullptr, g_vh, nullptr);
    }
}

__global__ __launch_bounds__(256) void out_mma_kernel(
    const float* __restrict__ bo, float* __restrict__ out)
{
    gemm_mma_body(g_ah, g_al, g_wh[3], bo, 1.0f, 0, out, nullptr, nullptr);
}

// ---------------------------------------------------------------------------
// HMMA flash attention: 2-pass fp16 (Q split x K single; P split x V single),
// shift-free log2-domain softmax, QK/PV pipelined, double-buffered K/V.
// ---------------------------------------------------------------------------
#define AT_QH 0
#define AT_QL (1 * GTILE)
#define AT_KV (2 * GTILE)          // 2 buffers x {KH, VH}
#define KV_KH 0
#define KV_VH (1 * GTILE)
#define KVBUF (2 * GTILE)
#define ATTN_SMEM (AT_KV + 2 * KVBUF)   // 110592 B

__device__ __forceinline__ void issue_kv(uint32_t base, int kt0, int h, int tid) {
#pragma unroll
    for (int i = 0; i < 4; i++) {
        int idx = tid + i * 256;
        int row = idx >> 3;
        int c16 = idx & 7;
        const uint32_t so = row * GSTRIDE + c16 * 16;
        const size_t go = (size_t)(kt0 + row) * DMODEL + h * HDIM + c16 * 8;
        cp16(base + KV_KH + so, g_kh + go);
        cp16(base + KV_VH + so, g_vh + go);
    }
}

__global__ __launch_bounds__(256, 1) void attn_mma_kernel()
{
    char* sm = smraw;
    const uint32_t smb = smem_u32(sm);
    const int tid  = threadIdx.x;
    const int lane = tid & 31;
    const int w    = tid >> 5;
    const int g    = lane >> 2;
    const int t    = lane & 3;
    const int h    = blockIdx.y;
    const int q0   = blockIdx.x * 128;

    issue_kv(smb + AT_KV, 0, h, tid);
    CP_COMMIT();

#pragma unroll
    for (int i = 0; i < 4; i++) {
        int idx = tid + i * 256;
        int row = idx >> 3;
        int c16 = idx & 7;
        const uint32_t so = row * GSTRIDE + c16 * 16;
        const size_t go = (size_t)(q0 + row) * DMODEL + h * HDIM + c16 * 8;
        *(uint4*)(sm + AT_QH + so) = *(const uint4*)(g_qh + go);
        *(uint4*)(sm + AT_QL + so) = *(const uint4*)(g_ql + go);
    }

    const uint32_t aOff = (uint32_t)(w * 16 + (lane & 15)) * GSTRIDE + ((lane >> 4) << 4);
    const uint32_t bOff = (uint32_t)((lane & 7) + ((lane >> 4) << 3)) * GSTRIDE
                        + (((lane >> 3) & 1) << 4);
    const uint32_t vOff = (uint32_t)((lane & 7) + (((lane >> 3) & 1) << 3)) * GSTRIDE
                        + ((lane >> 4) << 4);

    __syncthreads();

    // loop-invariant Q fragments (4 k-steps x hi/lo)
    uint32_t qfh[4][4], qfl[4][4];
#pragma unroll
    for (int ks = 0; ks < 4; ks++) {
        ldsm_x4(qfh[ks], smb + AT_QH + aOff + ks * 32);
        ldsm_x4(qfl[ks], smb + AT_QL + aOff + ks * 32);
    }

    float o[8][4];
#pragma unroll
    for (int i = 0; i < 8; i++)
#pragma unroll
        for (int c = 0; c < 4; c++) o[i][c] = 0.0f;
    float l0 = 0.0f, l1 = 0.0f;

    for (int it = 0; it < LSEQ / 128; it++) {
        const uint32_t kb = smb + AT_KV + (it & 1) * KVBUF;
        if (it < LSEQ / 128 - 1) {
            issue_kv(smb + AT_KV + ((it + 1) & 1) * KVBUF, (it + 1) * 128, h, tid);
            CP_COMMIT();
            CP_WAIT1();
        } else {
            CP_WAIT0();
        }
        __syncthreads();

        float s[16][4];
#pragma unroll
        for (int j = 0; j < 16; j++)
#pragma unroll
            for (int c = 0; c < 4; c++) s[j][c] = 0.0f;

        // ---- pipelined: QK(0); for jp: { QK(jp+1); exp+PV(jp) } ----
#pragma unroll
        for (int ph_i = 0; ph_i <= 4; ph_i++) {
            if (ph_i < 4) {
                const int jn = ph_i;
#pragma unroll
                for (int ks = 0; ks < 4; ks++) {
                    const uint32_t kOff = ks * 32;
                    uint32_t kha[4], khb[4];
                    ldsm_x4(kha, kb + KV_KH + bOff + (2 * jn) * (16 * GSTRIDE) + kOff);
                    ldsm_x4(khb, kb + KV_KH + bOff + (2 * jn + 1) * (16 * GSTRIDE) + kOff);
                    float* s0 = s[4 * jn + 0];
                    float* s1 = s[4 * jn + 1];
                    float* s2 = s[4 * jn + 2];
                    float* s3 = s[4 * jn + 3];
                    mma_h(s0, qfh[ks], &kha[0]);
                    mma_h(s1, qfh[ks], &kha[2]);
                    mma_h(s2, qfh[ks], &khb[0]);
                    mma_h(s3, qfh[ks], &khb[2]);
                    mma_h(s0, qfl[ks], &kha[0]);
                    mma_h(s1, qfl[ks], &kha[2]);
                    mma_h(s2, qfl[ks], &khb[0]);
                    mma_h(s3, qfl[ks], &khb[2]);
                }
            }
            if (ph_i >= 1) {
                const int jp = ph_i - 1;
                uint32_t ph[2][4], pl[2][4];
#pragma unroll
                for (int u = 0; u < 2; u++) {
                    const int j0 = 4 * jp + 2 * u;
                    float p00 = ex2(s[j0][0]),     p01 = ex2(s[j0][1]);
                    float p02 = ex2(s[j0][2]),     p03 = ex2(s[j0][3]);
                    float p10 = ex2(s[j0 + 1][0]), p11 = ex2(s[j0 + 1][1]);
                    float p12 = ex2(s[j0 + 1][2]), p13 = ex2(s[j0 + 1][3]);
                    l0 += (p00 + p01) + (p10 + p11);
                    l1 += (p02 + p03) + (p12 + p13);
                    pack_pair_h(p00, p01, ph[u][0], pl[u][0]);
                    pack_pair_h(p02, p03, ph[u][1], pl[u][1]);
                    pack_pair_h(p10, p11, ph[u][2], pl[u][2]);
                    pack_pair_h(p12, p13, ph[u][3], pl[u][3]);
                }
#pragma unroll
                for (int u = 0; u < 2; u++) {
                    const int kt = 2 * jp + u;
#pragma unroll
                    for (int dpp = 0; dpp < 2; dpp++) {
                        uint32_t vha[4], vhb[4];
                        const uint32_t va = vOff + kt * (16 * GSTRIDE) + (2 * dpp) * 32;
                        const uint32_t vb = vOff + kt * (16 * GSTRIDE) + (2 * dpp + 1) * 32;
                        ldsm_x4_t(vha, kb + KV_VH + va);
                        ldsm_x4_t(vhb, kb + KV_VH + vb);
                        float* o0 = o[4 * dpp + 0];
                        float* o1 = o[4 * dpp + 1];
                        float* o2 = o[4 * dpp + 2];
                        float* o3 = o[4 * dpp + 3];
                        mma_h(o0, ph[u], &vha[0]);
                        mma_h(o1, ph[u], &vha[2]);
                        mma_h(o2, ph[u], &vhb[0]);
                        mma_h(o3, ph[u], &vhb[2]);
                        mma_h(o0, pl[u], &vha[0]);
                        mma_h(o1, pl[u], &vha[2]);
                        mma_h(o2, pl[u], &vhb[0]);
                        mma_h(o3, pl[u], &vhb[2]);
                    }
                }
            }
        }
        __syncthreads();
    }

    // Final row-sum reduction and normalize; write split fp16
    l0 += __shfl_xor_sync(0xffffffffu, l0, 1);
    l0 += __shfl_xor_sync(0xffffffffu, l0, 2);
    l1 += __shfl_xor_sync(0xffffffffu, l1, 1);
    l1 += __shfl_xor_sync(0xffffffffu, l1, 2);
    const float inv0 = 1.0f / l0;
    const float inv1 = 1.0f / l1;
    const int row = q0 + w * 16 + g;
#pragma unroll
    for (int dt = 0; dt < 8; dt++) {
        const int col = h * HDIM + dt * 8 + t * 2;
        uint32_t h0, l0u, h1, l1u;
        pack_pair_h(o[dt][0] * inv0, o[dt][1] * inv0, h0, l0u);
        pack_pair_h(o[dt][2] * inv1, o[dt][3] * inv1, h1, l1u);
        const size_t o0 = (size_t)row * DMODEL + col;
        const size_t o1 = (size_t)(row + 8) * DMODEL + col;
        *(uint32_t*)(g_ah + o0) = h0;
        *(uint32_t*)(g_al + o0) = l0u;
        *(uint32_t*)(g_ah + o1) = h1;
        *(uint32_t*)(g_al + o1) = l1u;
    }
}

// ---------------------------------------------------------------------------
extern "C" void kernel_launch(void* const* d_in, const int* in_sizes, int n_in,
                              void* d_out, int out_size)
{
    const float* q  = (const float*)d_in[0];
    const float* k  = (const float*)d_in[1];
    const float* v  = (const float*)d_in[2];
    const float* wq = (const float*)d_in[3];
    const float* bq = (const float*)d_in[4];
    const float* wk = (const float*)d_in[5];
    const float* bk = (const float*)d_in[6];
    const float* wv = (const float*)d_in[7];
    const float* bv = (const float*)d_in[8];
    const float* wo = (const float*)d_in[9];
    const float* bo = (const float*)d_in[10];
    float* out = (float*)d_out;

    (void)in_sizes; (void)n_in; (void)out_size;

    cudaFuncSetAttribute(qkv_mma_kernel, cudaFuncAttributeMaxDynamicSharedMemorySize, GEMM_SMEM);
    cudaFuncSetAttribute(out_mma_kernel, cudaFuncAttributeMaxDynamicSharedMemorySize, GEMM_SMEM);
    cudaFuncSetAttribute(attn_mma_kernel, cudaFuncAttributeMaxDynamicSharedMemorySize, ATTN_SMEM);

    // 1. Split activations to fp16 hi/lo
    {
        dim3 grid(LSEQ * DMODEL / (256 * 4), 1, 3);
        conv_x_kernel<<<grid, 256>>>(q, k, v);
    }
    // 2. Transpose weights to single fp16
    {
        dim3 grid(DMODEL / 32, DMODEL / 32, 4);
        conv_w_kernel<<<grid, dim3(32, 8)>>>(wq, wk, wv, wo);
    }
    // 3. QKV projections (2-pass fp16 HMMA)
    {
        dim3 grid(DMODEL / 128, LSEQ / 128, 3);
        qkv_mma_kernel<<<grid, 256, GEMM_SMEM>>>(bq, bk, bv);
    }
    // 4. Attention (2-pass fp16 HMMA flash)
    {
        dim3 grid(LSEQ / 128, NHEAD);
        attn_mma_kernel<<<grid, 256, ATTN_SMEM>>>();
    }
    // 5. Output projection (2-pass fp16 HMMA)
    {
        dim3 grid(DMODEL / 128, LSEQ / 128);
        out_mma_kernel<<<grid, 256, GEMM_SMEM>>>(bo, out);
    }
}

// round 13
// speedup vs baseline: 1.0352x; 1.0352x over previous
#include <cuda_runtime.h>
#include <cuda_bf16.h>
#include <cstdint>
#include <math.h>

#define LSEQ   2048
#define DMODEL 1024
#define NHEAD  16
#define HDIM   64

// ---------------------------------------------------------------------------
// Scratch (__device__ globals; allocation-free rule)
// ---------------------------------------------------------------------------
__device__ __align__(16) __nv_bfloat16 g_xhi[3][LSEQ * DMODEL];
__device__ __align__(16) __nv_bfloat16 g_xlo[3][LSEQ * DMODEL];
__device__ __align__(16) __nv_bfloat16 g_whi[4][DMODEL * DMODEL];  // transposed: [n][k]
__device__ __align__(16) __nv_bfloat16 g_wlo[4][DMODEL * DMODEL];
__device__ __align__(16) __nv_bfloat16 g_qh[LSEQ * DMODEL];   // pre-scaled by 0.125*log2e
__device__ __align__(16) __nv_bfloat16 g_ql[LSEQ * DMODEL];
__device__ __align__(16) __nv_bfloat16 g_kh[LSEQ * DMODEL];
__device__ __align__(16) __nv_bfloat16 g_kl[LSEQ * DMODEL];
__device__ __align__(16) __nv_bfloat16 g_vh[LSEQ * DMODEL];
__device__ __align__(16) __nv_bfloat16 g_vl[LSEQ * DMODEL];
__device__ __align__(16) __nv_bfloat16 g_ahi[LSEQ * DMODEL];
__device__ __align__(16) __nv_bfloat16 g_alo[LSEQ * DMODEL];

// ---------------------------------------------------------------------------
// Base-ISA tensor-core + async-copy helpers
// ---------------------------------------------------------------------------
__device__ __forceinline__ uint32_t smem_u32(const void* p) {
    uint32_t a;
    asm("{ .reg .u64 t; cvta.to.shared.u64 t, %1; cvt.u32.u64 %0, t; }" : "=r"(a) : "l"(p));
    return a;
}
__device__ __forceinline__ void ldsm_x4(uint32_t* r, uint32_t addr) {
    asm volatile("ldmatrix.sync.aligned.m8n8.x4.shared.b16 {%0,%1,%2,%3}, [%4];"
                 : "=r"(r[0]), "=r"(r[1]), "=r"(r[2]), "=r"(r[3]) : "r"(addr));
}
__device__ __forceinline__ void ldsm_x4_t(uint32_t* r, uint32_t addr) {
    asm volatile("ldmatrix.sync.aligned.m8n8.x4.trans.shared.b16 {%0,%1,%2,%3}, [%4];"
                 : "=r"(r[0]), "=r"(r[1]), "=r"(r[2]), "=r"(r[3]) : "r"(addr));
}
__device__ __forceinline__ void mma16816(float* c, const uint32_t* a, const uint32_t* b) {
    asm volatile(
        "mma.sync.aligned.m16n8k16.row.col.f32.bf16.bf16.f32 "
        "{%0,%1,%2,%3}, {%4,%5,%6,%7}, {%8,%9}, {%0,%1,%2,%3};"
        : "+f"(c[0]), "+f"(c[1]), "+f"(c[2]), "+f"(c[3])
        : "r"(a[0]), "r"(a[1]), "r"(a[2]), "r"(a[3]), "r"(b[0]), "r"(b[1]));
}
__device__ __forceinline__ void cp16(uint32_t dst, const void* src) {
    asm volatile("cp.async.cg.shared.global [%0], [%1], 16;" :: "r"(dst), "l"(src));
}
#define CP_COMMIT() asm volatile("cp.async.commit_group;" ::: "memory")
#define CP_WAIT0()  asm volatile("cp.async.wait_group 0;" ::: "memory")
#define CP_WAIT1()  asm volatile("cp.async.wait_group 1;" ::: "memory")

__device__ __forceinline__ float ex2(float x) {
    float y;
    asm("ex2.approx.f32 %0, %1;" : "=f"(y) : "f"(x));
    return y;
}

// ---------------------------------------------------------------------------
// bf16 split helpers
// ---------------------------------------------------------------------------
__device__ __forceinline__ void split_bf16(float x, __nv_bfloat16& h, __nv_bfloat16& l) {
    h = __float2bfloat16(x);
    l = __float2bfloat16(x - __bfloat162float(h));
}
__device__ __forceinline__ void pack_pair(float a, float b, uint32_t& hi, uint32_t& lo) {
    __nv_bfloat162 h = __float22bfloat162_rn(make_float2(a, b));
    float ra = a - __bfloat162float(h.x);
    float rb = b - __bfloat162float(h.y);
    __nv_bfloat162 l = __float22bfloat162_rn(make_float2(ra, rb));
    hi = *reinterpret_cast<uint32_t*>(&h);
    lo = *reinterpret_cast<uint32_t*>(&l);
}

// Elementwise split of activations (q,k,v inputs), z-batched
__global__ void conv_x_kernel(const float* __restrict__ q, const float* __restrict__ k,
                              const float* __restrict__ v) {
    int z = blockIdx.z;
    const float* src = (z == 0) ? q : (z == 1) ? k : v;
    __nv_bfloat16* hi = g_xhi[z];
    __nv_bfloat16* lo = g_xlo[z];
    int i = (blockIdx.x * 256 + threadIdx.x) * 4;
    float4 xv = *(const float4*)(src + i);
    union { __nv_bfloat16 b[4]; uint2 u; } H, L;
    split_bf16(xv.x, H.b[0], L.b[0]);
    split_bf16(xv.y, H.b[1], L.b[1]);
    split_bf16(xv.z, H.b[2], L.b[2]);
    split_bf16(xv.w, H.b[3], L.b[3]);
    *(uint2*)(hi + i) = H.u;
    *(uint2*)(lo + i) = L.u;
}

// Transpose + split weights: W[k][n] -> Wt[n][k] hi/lo. 32x32 tiles, z-batched over 4.
__global__ void conv_w_kernel(const float* __restrict__ wq, const float* __restrict__ wk,
                              const float* __restrict__ wv, const float* __restrict__ wo) {
    __shared__ float tile[32][33];
    int z = blockIdx.z;
    const float* W = (z == 0) ? wq : (z == 1) ? wk : (z == 2) ? wv : wo;
    __nv_bfloat16* Thi = g_whi[z];
    __nv_bfloat16* Tlo = g_wlo[z];

    int n0 = blockIdx.x * 32;
    int k0 = blockIdx.y * 32;
    int tx = threadIdx.x, ty = threadIdx.y;
#pragma unroll
    for (int i = 0; i < 4; i++)
        tile[ty + i * 8][tx] = W[(size_t)(k0 + ty + i * 8) * DMODEL + n0 + tx];
    __syncthreads();
#pragma unroll
    for (int i = 0; i < 4; i++) {
        float val = tile[tx][ty + i * 8];
        __nv_bfloat16 h, l;
        split_bf16(val, h, l);
        size_t o = (size_t)(n0 + ty + i * 8) * DMODEL + k0 + tx;
        Thi[o] = h;
        Tlo[o] = l;
    }
}

// ---------------------------------------------------------------------------
// HMMA GEMM, 128-thread CTAs (2 co-resident per SM), tile 128(M)x64(N),
// BK=64, 2-stage cp.async ring, 3-pass bf16 split.
// ---------------------------------------------------------------------------
#define GSTRIDE 144                     // bytes per smem row: 64 bf16 + 8 pad
#define GTILE   (128 * GSTRIDE)         // 18432 B  (128-row tile)
#define BTILE   (64 * GSTRIDE)          // 9216 B   (64-row tile)
#define OF_AH   0
#define OF_AL   (1 * GTILE)
#define OF_BH   (2 * GTILE)
#define OF_BL   (2 * GTILE + BTILE)
#define GBUF    (2 * GTILE + 2 * BTILE) // 55296 B per stage
#define GEMM_SMEM (2 * GBUF)            // 110592 B -> 2 CTAs/SM

extern __shared__ char smraw[];

// A tile: 128 rows x 64 bf16, 128 threads -> 8 chunks each
__device__ __forceinline__ void issue_tile_a(uint32_t dst, const __nv_bfloat16* __restrict__ src,
                                             int row0, int k0, int tid) {
#pragma unroll
    for (int i = 0; i < 8; i++) {
        int idx = tid + i * 128;       // 0..1023
        int row = idx >> 3;            // 0..127
        int c16 = idx & 7;
        cp16(dst + row * GSTRIDE + c16 * 16,
             src + (size_t)(row0 + row) * DMODEL + k0 + c16 * 8);
    }
}
// B tile: 64 rows x 64 bf16, 128 threads -> 4 chunks each
__device__ __forceinline__ void issue_tile_b(uint32_t dst, const __nv_bfloat16* __restrict__ src,
                                             int row0, int k0, int tid) {
#pragma unroll
    for (int i = 0; i < 4; i++) {
        int idx = tid + i * 128;       // 0..511
        int row = idx >> 3;            // 0..63
        int c16 = idx & 7;
        cp16(dst + row * GSTRIDE + c16 * 16,
             src + (size_t)(row0 + row) * DMODEL + k0 + c16 * 8);
    }
}

__device__ __forceinline__ void issue_stage(uint32_t buf,
                                            const __nv_bfloat16* Ah, const __nv_bfloat16* Al,
                                            const __nv_bfloat16* Bh, const __nv_bfloat16* Bl,
                                            int bm, int bn, int k0, int tid) {
    issue_tile_a(buf + OF_AH, Ah, bm, k0, tid);
    issue_tile_a(buf + OF_AL, Al, bm, k0, tid);
    issue_tile_b(buf + OF_BH, Bh, bn, k0, tid);
    issue_tile_b(buf + OF_BL, Bl, bn, k0, tid);
    CP_COMMIT();
}

template <int SPLIT>
__device__ __forceinline__ void gemm_mma_body(
    const __nv_bfloat16* __restrict__ Ah, const __nv_bfloat16* __restrict__ Al,
    const __nv_bfloat16* __restrict__ Bh, const __nv_bfloat16* __restrict__ Bl,
    const float* __restrict__ bias, float oscale,
    float* __restrict__ C, __nv_bfloat16* __restrict__ Chi, __nv_bfloat16* __restrict__ Clo)
{
    const uint32_t smb = smem_u32(smraw);
    const int tid  = threadIdx.x;
    const int lane = tid & 31;
    const int wid  = tid >> 5;          // 0..3
    const int wm   = wid >> 1;          // 0..1 (M)
    const int wn   = wid & 1;           // 0..1 (N)
    const int bm   = blockIdx.y * 128;
    const int bn   = blockIdx.x * 64;
    const int NCH  = DMODEL / 64;       // 16

    float acc[4][4][4];
#pragma unroll
    for (int mi = 0; mi < 4; mi++)
#pragma unroll
        for (int ni = 0; ni < 4; ni++)
#pragma unroll
            for (int c = 0; c < 4; c++) acc[mi][ni][c] = 0.0f;

    const uint32_t aBase = (uint32_t)(wm * 64 + (lane & 15)) * GSTRIDE + ((lane >> 4) << 4);
    const uint32_t bBase = (uint32_t)(wn * 32 + (lane & 7) + ((lane >> 4) << 3)) * GSTRIDE
                         + (((lane >> 3) & 1) << 4);

    // prologue: stage chunk 0
    issue_stage(smb + 0 * GBUF, Ah, Al, Bh, Bl, bm, bn, 0, tid);

    for (int chunk = 0; chunk < NCH; chunk++) {
        // prefetch chunk+1 (its buffer was last read at compute chunk-1, done)
        if (chunk + 1 < NCH)
            issue_stage(smb + ((chunk + 1) & 1) * GBUF, Ah, Al, Bh, Bl,
                        bm, bn, (chunk + 1) * 64, tid);
        if (chunk + 1 < NCH) CP_WAIT1(); else CP_WAIT0();
        __syncthreads();   // chunk's data visible to all warps

        const uint32_t cb = smb + (chunk & 1) * GBUF;
#pragma unroll
        for (int kk = 0; kk < 4; kk++) {
            const uint32_t kOff = kk * 32;
            uint32_t ah[4][4], al[4][4], bh[2][4], bl[2][4];
#pragma unroll
            for (int mi = 0; mi < 4; mi++) {
                ldsm_x4(ah[mi], cb + OF_AH + aBase + mi * (16 * GSTRIDE) + kOff);
                ldsm_x4(al[mi], cb + OF_AL + aBase + mi * (16 * GSTRIDE) + kOff);
            }
#pragma unroll
            for (int nj = 0; nj < 2; nj++) {
                ldsm_x4(bh[nj], cb + OF_BH + bBase + nj * (16 * GSTRIDE) + kOff);
                ldsm_x4(bl[nj], cb + OF_BL + bBase + nj * (16 * GSTRIDE) + kOff);
            }
#pragma unroll
            for (int mi = 0; mi < 4; mi++)
#pragma unroll
                for (int ni = 0; ni < 4; ni++)
                    mma16816(acc[mi][ni], ah[mi], &bh[ni >> 1][(ni & 1) * 2]);
#pragma unroll
            for (int mi = 0; mi < 4; mi++)
#pragma unroll
                for (int ni = 0; ni < 4; ni++)
                    mma16816(acc[mi][ni], ah[mi], &bl[ni >> 1][(ni & 1) * 2]);
#pragma unroll
            for (int mi = 0; mi < 4; mi++)
#pragma unroll
                for (int ni = 0; ni < 4; ni++)
                    mma16816(acc[mi][ni], al[mi], &bh[ni >> 1][(ni & 1) * 2]);
        }
        __syncthreads();   // all warps done reading this buffer before overwrite
    }

    const int g = lane >> 2;
    const int t = lane & 3;
#pragma unroll
    for (int mi = 0; mi < 4; mi++) {
        const int row = bm + wm * 64 + mi * 16 + g;
#pragma unroll
        for (int ni = 0; ni < 4; ni++) {
            const int col = bn + wn * 32 + ni * 8 + t * 2;
            const float b0 = bias[col], b1 = bias[col + 1];
            float v0 = acc[mi][ni][0] + b0, v1 = acc[mi][ni][1] + b1;
            float v2 = acc[mi][ni][2] + b0, v3 = acc[mi][ni][3] + b1;
            if (SPLIT) {
                v0 *= oscale; v1 *= oscale; v2 *= oscale; v3 *= oscale;
                uint32_t h0, l0, h1, l1;
                pack_pair(v0, v1, h0, l0);
                pack_pair(v2, v3, h1, l1);
                const size_t o0 = (size_t)row * DMODEL + col;
                const size_t o1 = (size_t)(row + 8) * DMODEL + col;
                *(uint32_t*)(Chi + o0) = h0;
                *(uint32_t*)(Clo + o0) = l0;
                *(uint32_t*)(Chi + o1) = h1;
                *(uint32_t*)(Clo + o1) = l1;
            } else {
                *(float2*)(C + (size_t)row * DMODEL + col)       = make_float2(v0, v1);
                *(float2*)(C + (size_t)(row + 8) * DMODEL + col) = make_float2(v2, v3);
            }
        }
    }
}

// fold softmax scale AND log2(e) into Q so attention can use raw ex2
#define QSCALE (0.125f * 1.44269504088896340736f)

__global__ __launch_bounds__(128, 2) void qkv_mma_kernel(
    const float* __restrict__ bq, const float* __restrict__ bk, const float* __restrict__ bv)
{
    int z = blockIdx.z;
    const float* bias = (z == 0) ? bq : (z == 1) ? bk : bv;
    __nv_bfloat16* Chi = (z == 0) ? g_qh : (z == 1) ? g_kh : g_vh;
    __nv_bfloat16* Clo = (z == 0) ? g_ql : (z == 1) ? g_kl : g_vl;
    const float sc = (z == 0) ? QSCALE : 1.0f;
    gemm_mma_body<1>(g_xhi[z], g_xlo[z], g_whi[z], g_wlo[z], bias, sc, nullptr, Chi, Clo);
}

__global__ __launch_bounds__(128, 2) void out_mma_kernel(
    const float* __restrict__ bo, float* __restrict__ out)
{
    gemm_mma_body<0>(g_ahi, g_alo, g_whi[3], g_wlo[3], bo, 1.0f, out, nullptr, nullptr);
}

// ---------------------------------------------------------------------------
// HMMA flash attention (R10-exact, best measured): shift-free log2-domain
// softmax, QK/PV pipelined by jp-blocks, double-buffered K/V, q-tile 128.
// ---------------------------------------------------------------------------
#define AT_QH 0
#define AT_QL (1 * GTILE)
#define AT_KV (2 * GTILE)
#define KV_KH 0
#define KV_KL (1 * GTILE)
#define KV_VH (2 * GTILE)
#define KV_VL (3 * GTILE)
#define KVBUF (4 * GTILE)
#define ATTN_SMEM (AT_KV + 2 * KVBUF)

__device__ __forceinline__ void issue_kv(uint32_t base, int kt0, int h, int tid) {
#pragma unroll
    for (int i = 0; i < 4; i++) {
        int idx = tid + i * 256;
        int row = idx >> 3;
        int c16 = idx & 7;
        const uint32_t so = row * GSTRIDE + c16 * 16;
        const size_t go = (size_t)(kt0 + row) * DMODEL + h * HDIM + c16 * 8;
        cp16(base + KV_KH + so, g_kh + go);
        cp16(base + KV_KL + so, g_kl + go);
        cp16(base + KV_VH + so, g_vh + go);
        cp16(base + KV_VL + so, g_vl + go);
    }
}

__global__ __launch_bounds__(256, 1) void attn_mma_kernel()
{
    char* sm = smraw;
    const uint32_t smb = smem_u32(sm);
    const int tid  = threadIdx.x;
    const int lane = tid & 31;
    const int w    = tid >> 5;
    const int g    = lane >> 2;
    const int t    = lane & 3;
    const int h    = blockIdx.y;
    const int q0   = blockIdx.x * 128;

    issue_kv(smb + AT_KV, 0, h, tid);
    CP_COMMIT();

#pragma unroll
    for (int i = 0; i < 4; i++) {
        int idx = tid + i * 256;
        int row = idx >> 3;
        int c16 = idx & 7;
        const uint32_t so = row * GSTRIDE + c16 * 16;
        const size_t go = (size_t)(q0 + row) * DMODEL + h * HDIM + c16 * 8;
        *(uint4*)(sm + AT_QH + so) = *(const uint4*)(g_qh + go);
        *(uint4*)(sm + AT_QL + so) = *(const uint4*)(g_ql + go);
    }

    const uint32_t aOff = (uint32_t)(w * 16 + (lane & 15)) * GSTRIDE + ((lane >> 4) << 4);
    const uint32_t bOff = (uint32_t)((lane & 7) + ((lane >> 4) << 3)) * GSTRIDE
                        + (((lane >> 3) & 1) << 4);
    const uint32_t vOff = (uint32_t)((lane & 7) + (((lane >> 3) & 1) << 3)) * GSTRIDE
                        + ((lane >> 4) << 4);

    __syncthreads();

    uint32_t qfh[4][4], qfl[4][4];
#pragma unroll
    for (int ks = 0; ks < 4; ks++) {
        ldsm_x4(qfh[ks], smb + AT_QH + aOff + ks * 32);
        ldsm_x4(qfl[ks], smb + AT_QL + aOff + ks * 32);
    }

    float o[8][4];
#pragma unroll
    for (int i = 0; i < 8; i++)
#pragma unroll
        for (int c = 0; c < 4; c++) o[i][c] = 0.0f;
    float l0 = 0.0f, l1 = 0.0f;

    for (int it = 0; it < LSEQ / 128; it++) {
        const uint32_t kb = smb + AT_KV + (it & 1) * KVBUF;
        if (it < LSEQ / 128 - 1) {
            issue_kv(smb + AT_KV + ((it + 1) & 1) * KVBUF, (it + 1) * 128, h, tid);
            CP_COMMIT();
            CP_WAIT1();
        } else {
            CP_WAIT0();
        }
        __syncthreads();

        float s[16][4];
#pragma unroll
        for (int j = 0; j < 16; j++)
#pragma unroll
            for (int c = 0; c < 4; c++) s[j][c] = 0.0f;

        // ---- pipelined: QK(0); for jp: { QK(jp+1); exp+PV(jp) } ----
#pragma unroll
        for (int ph_i = 0; ph_i <= 4; ph_i++) {
            if (ph_i < 4) {
                const int jn = ph_i;
#pragma unroll
                for (int ks = 0; ks < 4; ks++) {
                    const uint32_t kOff = ks * 32;
                    uint32_t kha[4], kla[4], khb[4], klb[4];
                    const uint32_t ka  = bOff + (2 * jn) * (16 * GSTRIDE) + kOff;
                    const uint32_t ka2 = bOff + (2 * jn + 1) * (16 * GSTRIDE) + kOff;
                    ldsm_x4(kha, kb + KV_KH + ka);
                    ldsm_x4(kla, kb + KV_KL + ka);
                    ldsm_x4(khb, kb + KV_KH + ka2);
                    ldsm_x4(klb, kb + KV_KL + ka2);
                    float* s0 = s[4 * jn + 0];
                    float* s1 = s[4 * jn + 1];
                    float* s2 = s[4 * jn + 2];
                    float* s3 = s[4 * jn + 3];
                    mma16816(s0, qfh[ks], &kha[0]);
                    mma16816(s1, qfh[ks], &kha[2]);
                    mma16816(s2, qfh[ks], &khb[0]);
                    mma16816(s3, qfh[ks], &khb[2]);
                    mma16816(s0, qfh[ks], &kla[0]);
                    mma16816(s1, qfh[ks], &kla[2]);
                    mma16816(s2, qfh[ks], &klb[0]);
                    mma16816(s3, qfh[ks], &klb[2]);
                    mma16816(s0, qfl[ks], &kha[0]);
                    mma16816(s1, qfl[ks], &kha[2]);
                    mma16816(s2, qfl[ks], &khb[0]);
                    mma16816(s3, qfl[ks], &khb[2]);
                }
            }
            if (ph_i >= 1) {
                const int jp = ph_i - 1;
                uint32_t ph[2][4], pl[2][4];
#pragma unroll
                for (int u = 0; u < 2; u++) {
                    const int j0 = 4 * jp + 2 * u;
                    float p00 = ex2(s[j0][0]),     p01 = ex2(s[j0][1]);
                    float p02 = ex2(s[j0][2]),     p03 = ex2(s[j0][3]);
                    float p10 = ex2(s[j0 + 1][0]), p11 = ex2(s[j0 + 1][1]);
                    float p12 = ex2(s[j0 + 1][2]), p13 = ex2(s[j0 + 1][3]);
                    l0 += (p00 + p01) + (p10 + p11);
                    l1 += (p02 + p03) + (p12 + p13);
                    pack_pair(p00, p01, ph[u][0], pl[u][0]);
                    pack_pair(p02, p03, ph[u][1], pl[u][1]);
                    pack_pair(p10, p11, ph[u][2], pl[u][2]);
                    pack_pair(p12, p13, ph[u][3], pl[u][3]);
                }
#pragma unroll
                for (int u = 0; u < 2; u++) {
                    const int kt = 2 * jp + u;
#pragma unroll
                    for (int dpp = 0; dpp < 2; dpp++) {
                        uint32_t vha[4], vla[4], vhb[4], vlb[4];
                        const uint32_t va = vOff + kt * (16 * GSTRIDE) + (2 * dpp) * 32;
                        const uint32_t vb = vOff + kt * (16 * GSTRIDE) + (2 * dpp + 1) * 32;
                        ldsm_x4_t(vha, kb + KV_VH + va);
                        ldsm_x4_t(vla, kb + KV_VL + va);
                        ldsm_x4_t(vhb, kb + KV_VH + vb);
                        ldsm_x4_t(vlb, kb + KV_VL + vb);
                        float* o0 = o[4 * dpp + 0];
                        float* o1 = o[4 * dpp + 1];
                        float* o2 = o[4 * dpp + 2];
                        float* o3 = o[4 * dpp + 3];
                        mma16816(o0, ph[u], &vha[0]);
                        mma16816(o1, ph[u], &vha[2]);
                        mma16816(o2, ph[u], &vhb[0]);
                        mma16816(o3, ph[u], &vhb[2]);
                        mma16816(o0, pl[u], &vha[0]);
                        mma16816(o1, pl[u], &vha[2]);
                        mma16816(o2, pl[u], &vhb[0]);
                        mma16816(o3, pl[u], &vhb[2]);
                        mma16816(o0, ph[u], &vla[0]);
                        mma16816(o1, ph[u], &vla[2]);
                        mma16816(o2, ph[u], &vlb[0]);
                        mma16816(o3, ph[u], &vlb[2]);
                    }
                }
            }
        }
        __syncthreads();
    }

    // Final row-sum reduction and normalize; write split bf16
    l0 += __shfl_xor_sync(0xffffffffu, l0, 1);
    l0 += __shfl_xor_sync(0xffffffffu, l0, 2);
    l1 += __shfl_xor_sync(0xffffffffu, l1, 1);
    l1 += __shfl_xor_sync(0xffffffffu, l1, 2);
    const float inv0 = 1.0f / l0;
    const float inv1 = 1.0f / l1;
    const int row = q0 + w * 16 + g;
#pragma unroll
    for (int dt = 0; dt < 8; dt++) {
        const int col = h * HDIM + dt * 8 + t * 2;
        uint32_t h0, l0u, h1, l1u;
        pack_pair(o[dt][0] * inv0, o[dt][1] * inv0, h0, l0u);
        pack_pair(o[dt][2] * inv1, o[dt][3] * inv1, h1, l1u);
        const size_t o0 = (size_t)row * DMODEL + col;
        const size_t o1 = (size_t)(row + 8) * DMODEL + col;
        *(uint32_t*)(g_ahi + o0) = h0;
        *(uint32_t*)(g_alo + o0) = l0u;
        *(uint32_t*)(g_ahi + o1) = h1;
        *(uint32_t*)(g_alo + o1) = l1u;
    }
}

// ---------------------------------------------------------------------------
extern "C" void kernel_launch(void* const* d_in, const int* in_sizes, int n_in,
                              void* d_out, int out_size)
{
    const float* q  = (const float*)d_in[0];
    const float* k  = (const float*)d_in[1];
    const float* v  = (const float*)d_in[2];
    const float* wq = (const float*)d_in[3];
    const float* bq = (const float*)d_in[4];
    const float* wk = (const float*)d_in[5];
    const float* bk = (const float*)d_in[6];
    const float* wv = (const float*)d_in[7];
    const float* bv = (const float*)d_in[8];
    const float* wo = (const float*)d_in[9];
    const float* bo = (const float*)d_in[10];
    float* out = (float*)d_out;

    (void)in_sizes; (void)n_in; (void)out_size;

    cudaFuncSetAttribute(qkv_mma_kernel, cudaFuncAttributeMaxDynamicSharedMemorySize, GEMM_SMEM);
    cudaFuncSetAttribute(out_mma_kernel, cudaFuncAttributeMaxDynamicSharedMemorySize, GEMM_SMEM);
    cudaFuncSetAttribute(attn_mma_kernel, cudaFuncAttributeMaxDynamicSharedMemorySize, ATTN_SMEM);

    // 1. Split activations to bf16 hi/lo
    {
        dim3 grid(LSEQ * DMODEL / (256 * 4), 1, 3);
        conv_x_kernel<<<grid, 256>>>(q, k, v);
    }
    // 2. Transpose + split weights
    {
        dim3 grid(DMODEL / 32, DMODEL / 32, 4);
        conv_w_kernel<<<grid, dim3(32, 8)>>>(wq, wk, wv, wo);
    }
    // 3. QKV projections (128-thr CTAs, 2/SM, 2-stage ring)
    {
        dim3 grid(DMODEL / 64, LSEQ / 128, 3);
        qkv_mma_kernel<<<grid, 128, GEMM_SMEM>>>(bq, bk, bv);
    }
    // 4. Attention (R10-exact)
    {
        dim3 grid(LSEQ / 128, NHEAD);
        attn_mma_kernel<<<grid, 256, ATTN_SMEM>>>();
    }
    // 5. Output projection (128-thr CTAs, 2/SM, 2-stage ring)
    {
        dim3 grid(DMODEL / 64, LSEQ / 128);
        out_mma_kernel<<<grid, 128, GEMM_SMEM>>>(bo, out);
    }
}

// round 14
// speedup vs baseline: 1.0560x; 1.0201x over previous
#include <cuda_runtime.h>
#include <cuda_bf16.h>
#include <cstdint>
#include <math.h>

#define LSEQ   2048
#define DMODEL 1024
#define NHEAD  16
#define HDIM   64

// ---------------------------------------------------------------------------
// Scratch (__device__ globals; allocation-free rule)
// ---------------------------------------------------------------------------
__device__ __align__(16) __nv_bfloat16 g_xhi[3][LSEQ * DMODEL];
__device__ __align__(16) __nv_bfloat16 g_xlo[3][LSEQ * DMODEL];
__device__ __align__(16) __nv_bfloat16 g_whi[4][DMODEL * DMODEL];  // transposed: [n][k]
__device__ __align__(16) __nv_bfloat16 g_wlo[4][DMODEL * DMODEL];
__device__ __align__(16) __nv_bfloat16 g_qh[LSEQ * DMODEL];   // pre-scaled by 0.125*log2e
__device__ __align__(16) __nv_bfloat16 g_ql[LSEQ * DMODEL];
__device__ __align__(16) __nv_bfloat16 g_kh[LSEQ * DMODEL];
__device__ __align__(16) __nv_bfloat16 g_kl[LSEQ * DMODEL];
__device__ __align__(16) __nv_bfloat16 g_vh[LSEQ * DMODEL];
__device__ __align__(16) __nv_bfloat16 g_vl[LSEQ * DMODEL];
__device__ __align__(16) __nv_bfloat16 g_ahi[LSEQ * DMODEL];
__device__ __align__(16) __nv_bfloat16 g_alo[LSEQ * DMODEL];

// ---------------------------------------------------------------------------
// Base-ISA tensor-core + async-copy helpers
// ---------------------------------------------------------------------------
__device__ __forceinline__ uint32_t smem_u32(const void* p) {
    uint32_t a;
    asm("{ .reg .u64 t; cvta.to.shared.u64 t, %1; cvt.u32.u64 %0, t; }" : "=r"(a) : "l"(p));
    return a;
}
__device__ __forceinline__ void ldsm_x4(uint32_t* r, uint32_t addr) {
    asm volatile("ldmatrix.sync.aligned.m8n8.x4.shared.b16 {%0,%1,%2,%3}, [%4];"
                 : "=r"(r[0]), "=r"(r[1]), "=r"(r[2]), "=r"(r[3]) : "r"(addr));
}
__device__ __forceinline__ void ldsm_x4_t(uint32_t* r, uint32_t addr) {
    asm volatile("ldmatrix.sync.aligned.m8n8.x4.trans.shared.b16 {%0,%1,%2,%3}, [%4];"
                 : "=r"(r[0]), "=r"(r[1]), "=r"(r[2]), "=r"(r[3]) : "r"(addr));
}
__device__ __forceinline__ void mma16816(float* c, const uint32_t* a, const uint32_t* b) {
    asm volatile(
        "mma.sync.aligned.m16n8k16.row.col.f32.bf16.bf16.f32 "
        "{%0,%1,%2,%3}, {%4,%5,%6,%7}, {%8,%9}, {%0,%1,%2,%3};"
        : "+f"(c[0]), "+f"(c[1]), "+f"(c[2]), "+f"(c[3])
        : "r"(a[0]), "r"(a[1]), "r"(a[2]), "r"(a[3]), "r"(b[0]), "r"(b[1]));
}
__device__ __forceinline__ void cp16(uint32_t dst, const void* src) {
    asm volatile("cp.async.cg.shared.global [%0], [%1], 16;" :: "r"(dst), "l"(src));
}
#define CP_COMMIT() asm volatile("cp.async.commit_group;" ::: "memory")
#define CP_WAIT0()  asm volatile("cp.async.wait_group 0;" ::: "memory")
#define CP_WAIT1()  asm volatile("cp.async.wait_group 1;" ::: "memory")

__device__ __forceinline__ float ex2(float x) {
    float y;
    asm("ex2.approx.f32 %0, %1;" : "=f"(y) : "f"(x));
    return y;
}

// ---------------------------------------------------------------------------
// bf16 split helpers
// ---------------------------------------------------------------------------
__device__ __forceinline__ void split_bf16(float x, __nv_bfloat16& h, __nv_bfloat16& l) {
    h = __float2bfloat16(x);
    l = __float2bfloat16(x - __bfloat162float(h));
}
__device__ __forceinline__ void pack_pair(float a, float b, uint32_t& hi, uint32_t& lo) {
    __nv_bfloat162 h = __float22bfloat162_rn(make_float2(a, b));
    float ra = a - __bfloat162float(h.x);
    float rb = b - __bfloat162float(h.y);
    __nv_bfloat162 l = __float22bfloat162_rn(make_float2(ra, rb));
    hi = *reinterpret_cast<uint32_t*>(&h);
    lo = *reinterpret_cast<uint32_t*>(&l);
}

// Elementwise split of activations (q,k,v inputs), z-batched
__global__ void conv_x_kernel(const float* __restrict__ q, const float* __restrict__ k,
                              const float* __restrict__ v) {
    int z = blockIdx.z;
    const float* src = (z == 0) ? q : (z == 1) ? k : v;
    __nv_bfloat16* hi = g_xhi[z];
    __nv_bfloat16* lo = g_xlo[z];
    int i = (blockIdx.x * 256 + threadIdx.x) * 4;
    float4 xv = *(const float4*)(src + i);
    union { __nv_bfloat16 b[4]; uint2 u; } H, L;
    split_bf16(xv.x, H.b[0], L.b[0]);
    split_bf16(xv.y, H.b[1], L.b[1]);
    split_bf16(xv.z, H.b[2], L.b[2]);
    split_bf16(xv.w, H.b[3], L.b[3]);
    *(uint2*)(hi + i) = H.u;
    *(uint2*)(lo + i) = L.u;
}

// Transpose + split weights: W[k][n] -> Wt[n][k] hi/lo. 32x32 tiles, z-batched over 4.
__global__ void conv_w_kernel(const float* __restrict__ wq, const float* __restrict__ wk,
                              const float* __restrict__ wv, const float* __restrict__ wo) {
    __shared__ float tile[32][33];
    int z = blockIdx.z;
    const float* W = (z == 0) ? wq : (z == 1) ? wk : (z == 2) ? wv : wo;
    __nv_bfloat16* Thi = g_whi[z];
    __nv_bfloat16* Tlo = g_wlo[z];

    int n0 = blockIdx.x * 32;
    int k0 = blockIdx.y * 32;
    int tx = threadIdx.x, ty = threadIdx.y;
#pragma unroll
    for (int i = 0; i < 4; i++)
        tile[ty + i * 8][tx] = W[(size_t)(k0 + ty + i * 8) * DMODEL + n0 + tx];
    __syncthreads();
#pragma unroll
    for (int i = 0; i < 4; i++) {
        float val = tile[tx][ty + i * 8];
        __nv_bfloat16 h, l;
        split_bf16(val, h, l);
        size_t o = (size_t)(n0 + ty + i * 8) * DMODEL + k0 + tx;
        Thi[o] = h;
        Tlo[o] = l;
    }
}

// ---------------------------------------------------------------------------
// HMMA GEMM (R10 shape, proven best): 3-stage cp.async ring, CTA 128x128,
// BK=64, 256 threads, 3-pass bf16 split.
// ---------------------------------------------------------------------------
#define GSTRIDE 144                     // bytes per smem row: 64 bf16 + 8 pad
#define GTILE   (128 * GSTRIDE)         // 18432 B
#define BTILE   (64 * GSTRIDE)          // 9216 B
#define OF_AH   0
#define OF_AL   (1 * GTILE)
#define OF_BH   (2 * GTILE)
#define OF_BL   (3 * GTILE)
#define GBUF    (4 * GTILE)             // 73728 B per stage
#define GEMM_SMEM (3 * GBUF)            // 221184 B

extern __shared__ char smraw[];

__device__ __forceinline__ void issue_tile(uint32_t dst, const __nv_bfloat16* __restrict__ src,
                                           int row0, int k0, int tid) {
#pragma unroll
    for (int i = 0; i < 4; i++) {
        int idx = tid + i * 256;
        int row = idx >> 3;
        int c16 = idx & 7;
        cp16(dst + row * GSTRIDE + c16 * 16,
             src + (size_t)(row0 + row) * DMODEL + k0 + c16 * 8);
    }
}

__device__ __forceinline__ void issue_stage(uint32_t buf,
                                            const __nv_bfloat16* Ah, const __nv_bfloat16* Al,
                                            const __nv_bfloat16* Bh, const __nv_bfloat16* Bl,
                                            int bm, int bn, int k0, int tid) {
    issue_tile(buf + OF_AH, Ah, bm, k0, tid);
    issue_tile(buf + OF_AL, Al, bm, k0, tid);
    issue_tile(buf + OF_BH, Bh, bn, k0, tid);
    issue_tile(buf + OF_BL, Bl, bn, k0, tid);
    CP_COMMIT();
}

template <int SPLIT>
__device__ __forceinline__ void gemm_mma_body(
    const __nv_bfloat16* __restrict__ Ah, const __nv_bfloat16* __restrict__ Al,
    const __nv_bfloat16* __restrict__ Bh, const __nv_bfloat16* __restrict__ Bl,
    const float* __restrict__ bias, float oscale,
    float* __restrict__ C, __nv_bfloat16* __restrict__ Chi, __nv_bfloat16* __restrict__ Clo)
{
    const uint32_t smb = smem_u32(smraw);
    const int tid  = threadIdx.x;
    const int lane = tid & 31;
    const int wid  = tid >> 5;
    const int wm   = wid >> 2;
    const int wn   = wid & 3;
    const int bm   = blockIdx.y * 128;
    const int bn   = blockIdx.x * 128;
    const int NCH  = DMODEL / 64;       // 16

    float acc[4][4][4];
#pragma unroll
    for (int mi = 0; mi < 4; mi++)
#pragma unroll
        for (int ni = 0; ni < 4; ni++)
#pragma unroll
            for (int c = 0; c < 4; c++) acc[mi][ni][c] = 0.0f;

    const uint32_t aBase = (uint32_t)(wm * 64 + (lane & 15)) * GSTRIDE + ((lane >> 4) << 4);
    const uint32_t bBase = (uint32_t)(wn * 32 + (lane & 7) + ((lane >> 4) << 3)) * GSTRIDE
                         + (((lane >> 3) & 1) << 4);

    issue_stage(smb + 0 * GBUF, Ah, Al, Bh, Bl, bm, bn, 0, tid);
    issue_stage(smb + 1 * GBUF, Ah, Al, Bh, Bl, bm, bn, 64, tid);

    int cbi = 0;
    for (int chunk = 0; chunk < NCH; chunk++) {
        if (chunk < NCH - 1) CP_WAIT1(); else CP_WAIT0();
        __syncthreads();
        if (chunk + 2 < NCH) {
            int nbi = cbi + 2; if (nbi >= 3) nbi -= 3;
            issue_stage(smb + nbi * GBUF, Ah, Al, Bh, Bl, bm, bn, (chunk + 2) * 64, tid);
        }
        const uint32_t cb = smb + cbi * GBUF;

#pragma unroll
        for (int kk = 0; kk < 4; kk++) {
            const uint32_t kOff = kk * 32;
            uint32_t ah[4][4], al[4][4], bh[2][4], bl[2][4];
#pragma unroll
            for (int mi = 0; mi < 4; mi++) {
                ldsm_x4(ah[mi], cb + OF_AH + aBase + mi * (16 * GSTRIDE) + kOff);
                ldsm_x4(al[mi], cb + OF_AL + aBase + mi * (16 * GSTRIDE) + kOff);
            }
#pragma unroll
            for (int nj = 0; nj < 2; nj++) {
                ldsm_x4(bh[nj], cb + OF_BH + bBase + nj * (16 * GSTRIDE) + kOff);
                ldsm_x4(bl[nj], cb + OF_BL + bBase + nj * (16 * GSTRIDE) + kOff);
            }
#pragma unroll
            for (int mi = 0; mi < 4; mi++)
#pragma unroll
                for (int ni = 0; ni < 4; ni++)
                    mma16816(acc[mi][ni], ah[mi], &bh[ni >> 1][(ni & 1) * 2]);
#pragma unroll
            for (int mi = 0; mi < 4; mi++)
#pragma unroll
                for (int ni = 0; ni < 4; ni++)
                    mma16816(acc[mi][ni], ah[mi], &bl[ni >> 1][(ni & 1) * 2]);
#pragma unroll
            for (int mi = 0; mi < 4; mi++)
#pragma unroll
                for (int ni = 0; ni < 4; ni++)
                    mma16816(acc[mi][ni], al[mi], &bh[ni >> 1][(ni & 1) * 2]);
        }
        if (++cbi >= 3) cbi -= 3;
    }

    const int g = lane >> 2;
    const int t = lane & 3;
#pragma unroll
    for (int mi = 0; mi < 4; mi++) {
        const int row = bm + wm * 64 + mi * 16 + g;
#pragma unroll
        for (int ni = 0; ni < 4; ni++) {
            const int col = bn + wn * 32 + ni * 8 + t * 2;
            const float b0 = bias[col], b1 = bias[col + 1];
            float v0 = acc[mi][ni][0] + b0, v1 = acc[mi][ni][1] + b1;
            float v2 = acc[mi][ni][2] + b0, v3 = acc[mi][ni][3] + b1;
            if (SPLIT) {
                v0 *= oscale; v1 *= oscale; v2 *= oscale; v3 *= oscale;
                uint32_t h0, l0, h1, l1;
                pack_pair(v0, v1, h0, l0);
                pack_pair(v2, v3, h1, l1);
                const size_t o0 = (size_t)row * DMODEL + col;
                const size_t o1 = (size_t)(row + 8) * DMODEL + col;
                *(uint32_t*)(Chi + o0) = h0;
                *(uint32_t*)(Clo + o0) = l0;
                *(uint32_t*)(Chi + o1) = h1;
                *(uint32_t*)(Clo + o1) = l1;
            } else {
                *(float2*)(C + (size_t)row * DMODEL + col)       = make_float2(v0, v1);
                *(float2*)(C + (size_t)(row + 8) * DMODEL + col) = make_float2(v2, v3);
            }
        }
    }
}

// fold softmax scale AND log2(e) into Q so attention can use raw ex2
#define QSCALE (0.125f * 1.44269504088896340736f)

__global__ __launch_bounds__(256) void qkv_mma_kernel(
    const float* __restrict__ bq, const float* __restrict__ bk, const float* __restrict__ bv)
{
    int z = blockIdx.z;
    const float* bias = (z == 0) ? bq : (z == 1) ? bk : bv;
    __nv_bfloat16* Chi = (z == 0) ? g_qh : (z == 1) ? g_kh : g_vh;
    __nv_bfloat16* Clo = (z == 0) ? g_ql : (z == 1) ? g_kl : g_vl;
    const float sc = (z == 0) ? QSCALE : 1.0f;
    gemm_mma_body<1>(g_xhi[z], g_xlo[z], g_whi[z], g_wlo[z], bias, sc, nullptr, Chi, Clo);
}

__global__ __launch_bounds__(256) void out_mma_kernel(
    const float* __restrict__ bo, float* __restrict__ out)
{
    gemm_mma_body<0>(g_ahi, g_alo, g_whi[3], g_wlo[3], bo, 1.0f, out, nullptr, nullptr);
}

// ---------------------------------------------------------------------------
// HMMA flash attention: 128-thread CTAs (2 co-resident/SM), q-tile 64,
// key-tile 64, DOUBLE-buffered K/V, shift-free log2 softmax, QK/PV pipelined.
// Per-warp structure (16 q-rows) identical to R10.
// ---------------------------------------------------------------------------
#define AT_QH 0
#define AT_QL (1 * BTILE)
#define AT_KV (2 * BTILE)           // 2 buffers x {KH,KL,VH,VL}, 64-row tiles
#define KV_KH 0
#define KV_KL (1 * BTILE)
#define KV_VH (2 * BTILE)
#define KV_VL (3 * BTILE)
#define KVBUF (4 * BTILE)           // 36864 B
#define ATTN_SMEM (AT_KV + 2 * KVBUF)   // 92160 B -> 2 CTAs/SM

__device__ __forceinline__ void issue_kv64(uint32_t base, int kt0, int h, int tid) {
#pragma unroll
    for (int i = 0; i < 4; i++) {
        int idx = tid + i * 128;       // 0..511
        int row = idx >> 3;            // 0..63
        int c16 = idx & 7;
        const uint32_t so = row * GSTRIDE + c16 * 16;
        const size_t go = (size_t)(kt0 + row) * DMODEL + h * HDIM + c16 * 8;
        cp16(base + KV_KH + so, g_kh + go);
        cp16(base + KV_KL + so, g_kl + go);
        cp16(base + KV_VH + so, g_vh + go);
        cp16(base + KV_VL + so, g_vl + go);
    }
}

__global__ __launch_bounds__(128, 2) void attn_mma_kernel()
{
    char* sm = smraw;
    const uint32_t smb = smem_u32(sm);
    const int tid  = threadIdx.x;
    const int lane = tid & 31;
    const int w    = tid >> 5;          // 0..3
    const int g    = lane >> 2;
    const int t    = lane & 3;
    const int h    = blockIdx.y;
    const int q0   = blockIdx.x * 64;
    const int NIT  = LSEQ / 64;         // 32

    // stage K/V tile 0 (async), then fill Q (64 rows, pre-scaled+split)
    issue_kv64(smb + AT_KV, 0, h, tid);
    CP_COMMIT();

#pragma unroll
    for (int i = 0; i < 4; i++) {
        int idx = tid + i * 128;
        int row = idx >> 3;            // 0..63
        int c16 = idx & 7;
        const uint32_t so = row * GSTRIDE + c16 * 16;
        const size_t go = (size_t)(q0 + row) * DMODEL + h * HDIM + c16 * 8;
        *(uint4*)(sm + AT_QH + so) = *(const uint4*)(g_qh + go);
        *(uint4*)(sm + AT_QL + so) = *(const uint4*)(g_ql + go);
    }

    const uint32_t aOff = (uint32_t)(w * 16 + (lane & 15)) * GSTRIDE + ((lane >> 4) << 4);
    const uint32_t bOff = (uint32_t)((lane & 7) + ((lane >> 4) << 3)) * GSTRIDE
                        + (((lane >> 3) & 1) << 4);
    const uint32_t vOff = (uint32_t)((lane & 7) + (((lane >> 3) & 1) << 3)) * GSTRIDE
                        + ((lane >> 4) << 4);

    __syncthreads();   // Q stores visible

    // loop-invariant Q fragments (4 k-steps x hi/lo)
    uint32_t qfh[4][4], qfl[4][4];
#pragma unroll
    for (int ks = 0; ks < 4; ks++) {
        ldsm_x4(qfh[ks], smb + AT_QH + aOff + ks * 32);
        ldsm_x4(qfl[ks], smb + AT_QL + aOff + ks * 32);
    }

    float o[8][4];
#pragma unroll
    for (int i = 0; i < 8; i++)
#pragma unroll
        for (int c = 0; c < 4; c++) o[i][c] = 0.0f;
    float l0 = 0.0f, l1 = 0.0f;

    for (int it = 0; it < NIT; it++) {
        const uint32_t kb = smb + AT_KV + (it & 1) * KVBUF;
        if (it < NIT - 1) {
            issue_kv64(smb + AT_KV + ((it + 1) & 1) * KVBUF, (it + 1) * 64, h, tid);
            CP_COMMIT();
            CP_WAIT1();
        } else {
            CP_WAIT0();
        }
        __syncthreads();

        // S tile: 16 q-rows x 64 keys -> s[8][4] (8 n-fragments of 8 cols)
        float s[8][4];
#pragma unroll
        for (int j = 0; j < 8; j++)
#pragma unroll
            for (int c = 0; c < 4; c++) s[j][c] = 0.0f;

        // ---- pipelined: QK(0); { QK(1); exp+PV(0) }; exp+PV(1) ----
#pragma unroll
        for (int ph_i = 0; ph_i <= 2; ph_i++) {
            if (ph_i < 2) {
                const int jn = ph_i;   // jp block = 32 keys = key-16 blocks 2jn, 2jn+1
#pragma unroll
                for (int ks = 0; ks < 4; ks++) {
                    const uint32_t kOff = ks * 32;
                    uint32_t kha[4], kla[4], khb[4], klb[4];
                    const uint32_t ka  = bOff + (2 * jn) * (16 * GSTRIDE) + kOff;
                    const uint32_t ka2 = bOff + (2 * jn + 1) * (16 * GSTRIDE) + kOff;
                    ldsm_x4(kha, kb + KV_KH + ka);
                    ldsm_x4(kla, kb + KV_KL + ka);
                    ldsm_x4(khb, kb + KV_KH + ka2);
                    ldsm_x4(klb, kb + KV_KL + ka2);
                    float* s0 = s[4 * jn + 0];
                    float* s1 = s[4 * jn + 1];
                    float* s2 = s[4 * jn + 2];
                    float* s3 = s[4 * jn + 3];
                    mma16816(s0, qfh[ks], &kha[0]);
                    mma16816(s1, qfh[ks], &kha[2]);
                    mma16816(s2, qfh[ks], &khb[0]);
                    mma16816(s3, qfh[ks], &khb[2]);
                    mma16816(s0, qfh[ks], &kla[0]);
                    mma16816(s1, qfh[ks], &kla[2]);
                    mma16816(s2, qfh[ks], &klb[0]);
                    mma16816(s3, qfh[ks], &klb[2]);
                    mma16816(s0, qfl[ks], &kha[0]);
                    mma16816(s1, qfl[ks], &kha[2]);
                    mma16816(s2, qfl[ks], &khb[0]);
                    mma16816(s3, qfl[ks], &khb[2]);
                }
            }
            if (ph_i >= 1) {
                const int jp = ph_i - 1;
                uint32_t ph[2][4], pl[2][4];
#pragma unroll
                for (int u = 0; u < 2; u++) {
                    const int j0 = 4 * jp + 2 * u;
                    float p00 = ex2(s[j0][0]),     p01 = ex2(s[j0][1]);
                    float p02 = ex2(s[j0][2]),     p03 = ex2(s[j0][3]);
                    float p10 = ex2(s[j0 + 1][0]), p11 = ex2(s[j0 + 1][1]);
                    float p12 = ex2(s[j0 + 1][2]), p13 = ex2(s[j0 + 1][3]);
                    l0 += (p00 + p01) + (p10 + p11);
                    l1 += (p02 + p03) + (p12 + p13);
                    pack_pair(p00, p01, ph[u][0], pl[u][0]);
                    pack_pair(p02, p03, ph[u][1], pl[u][1]);
                    pack_pair(p10, p11, ph[u][2], pl[u][2]);
                    pack_pair(p12, p13, ph[u][3], pl[u][3]);
                }
#pragma unroll
                for (int u = 0; u < 2; u++) {
                    const int kt = 2 * jp + u;   // key-16 block 0..3
#pragma unroll
                    for (int dpp = 0; dpp < 2; dpp++) {
                        uint32_t vha[4], vla[4], vhb[4], vlb[4];
                        const uint32_t va = vOff + kt * (16 * GSTRIDE) + (2 * dpp) * 32;
                        const uint32_t vb = vOff + kt * (16 * GSTRIDE) + (2 * dpp + 1) * 32;
                        ldsm_x4_t(vha, kb + KV_VH + va);
                        ldsm_x4_t(vla, kb + KV_VL + va);
                        ldsm_x4_t(vhb, kb + KV_VH + vb);
                        ldsm_x4_t(vlb, kb + KV_VL + vb);
                        float* o0 = o[4 * dpp + 0];
                        float* o1 = o[4 * dpp + 1];
                        float* o2 = o[4 * dpp + 2];
                        float* o3 = o[4 * dpp + 3];
                        mma16816(o0, ph[u], &vha[0]);
                        mma16816(o1, ph[u], &vha[2]);
                        mma16816(o2, ph[u], &vhb[0]);
                        mma16816(o3, ph[u], &vhb[2]);
                        mma16816(o0, pl[u], &vha[0]);
                        mma16816(o1, pl[u], &vha[2]);
                        mma16816(o2, pl[u], &vhb[0]);
                        mma16816(o3, pl[u], &vhb[2]);
                        mma16816(o0, ph[u], &vla[0]);
                        mma16816(o1, ph[u], &vla[2]);
                        mma16816(o2, ph[u], &vlb[0]);
                        mma16816(o3, ph[u], &vlb[2]);
                    }
                }
            }
        }
        __syncthreads();   // all warps done with this K/V buffer
    }

    // Final row-sum reduction and normalize; write split bf16
    l0 += __shfl_xor_sync(0xffffffffu, l0, 1);
    l0 += __shfl_xor_sync(0xffffffffu, l0, 2);
    l1 += __shfl_xor_sync(0xffffffffu, l1, 1);
    l1 += __shfl_xor_sync(0xffffffffu, l1, 2);
    const float inv0 = 1.0f / l0;
    const float inv1 = 1.0f / l1;
    const int row = q0 + w * 16 + g;
#pragma unroll
    for (int dt = 0; dt < 8; dt++) {
        const int col = h * HDIM + dt * 8 + t * 2;
        uint32_t h0, l0u, h1, l1u;
        pack_pair(o[dt][0] * inv0, o[dt][1] * inv0, h0, l0u);
        pack_pair(o[dt][2] * inv1, o[dt][3] * inv1, h1, l1u);
        const size_t o0 = (size_t)row * DMODEL + col;
        const size_t o1 = (size_t)(row + 8) * DMODEL + col;
        *(uint32_t*)(g_ahi + o0) = h0;
        *(uint32_t*)(g_alo + o0) = l0u;
        *(uint32_t*)(g_ahi + o1) = h1;
        *(uint32_t*)(g_alo + o1) = l1u;
    }
}

// ---------------------------------------------------------------------------
extern "C" void kernel_launch(void* const* d_in, const int* in_sizes, int n_in,
                              void* d_out, int out_size)
{
    const float* q  = (const float*)d_in[0];
    const float* k  = (const float*)d_in[1];
    const float* v  = (const float*)d_in[2];
    const float* wq = (const float*)d_in[3];
    const float* bq = (const float*)d_in[4];
    const float* wk = (const float*)d_in[5];
    const float* bk = (const float*)d_in[6];
    const float* wv = (const float*)d_in[7];
    const float* bv = (const float*)d_in[8];
    const float* wo = (const float*)d_in[9];
    const float* bo = (const float*)d_in[10];
    float* out = (float*)d_out;

    (void)in_sizes; (void)n_in; (void)out_size;

    cudaFuncSetAttribute(qkv_mma_kernel, cudaFuncAttributeMaxDynamicSharedMemorySize, GEMM_SMEM);
    cudaFuncSetAttribute(out_mma_kernel, cudaFuncAttributeMaxDynamicSharedMemorySize, GEMM_SMEM);
    cudaFuncSetAttribute(attn_mma_kernel, cudaFuncAttributeMaxDynamicSharedMemorySize, ATTN_SMEM);

    // 1. Split activations to bf16 hi/lo
    {
        dim3 grid(LSEQ * DMODEL / (256 * 4), 1, 3);
        conv_x_kernel<<<grid, 256>>>(q, k, v);
    }
    // 2. Transpose + split weights
    {
        dim3 grid(DMODEL / 32, DMODEL / 32, 4);
        conv_w_kernel<<<grid, dim3(32, 8)>>>(wq, wk, wv, wo);
    }
    // 3. QKV projections (R10 GEMM: 256-thr, 3-stage ring)
    {
        dim3 grid(DMODEL / 128, LSEQ / 128, 3);
        qkv_mma_kernel<<<grid, 256, GEMM_SMEM>>>(bq, bk, bv);
    }
    // 4. Attention (q-tile 64, 2 CTAs/SM, double-buffered)
    {
        dim3 grid(LSEQ / 64, NHEAD);
        attn_mma_kernel<<<grid, 128, ATTN_SMEM>>>();
    }
    // 5. Output projection (R10 GEMM)
    {
        dim3 grid(DMODEL / 128, LSEQ / 128);
        out_mma_kernel<<<grid, 256, GEMM_SMEM>>>(bo, out);
    }
}

// round 17
// speedup vs baseline: 1.0823x; 1.0249x over previous
#include <cuda_runtime.h>
#include <cuda_bf16.h>
#include <cstdint>
#include <math.h>

#define LSEQ   2048
#define DMODEL 1024
#define NHEAD  16
#define HDIM   64

// ---------------------------------------------------------------------------
// Scratch (__device__ globals; allocation-free rule)
// ---------------------------------------------------------------------------
__device__ __align__(16) __nv_bfloat16 g_xhi[3][LSEQ * DMODEL];
__device__ __align__(16) __nv_bfloat16 g_xlo[3][LSEQ * DMODEL];
__device__ __align__(16) __nv_bfloat16 g_whi[4][DMODEL * DMODEL];  // transposed: [n][k]
__device__ __align__(16) __nv_bfloat16 g_wlo[4][DMODEL * DMODEL];
__device__ __align__(16) __nv_bfloat16 g_qh[LSEQ * DMODEL];   // pre-scaled by 0.125*log2e
__device__ __align__(16) __nv_bfloat16 g_ql[LSEQ * DMODEL];
__device__ __align__(16) __nv_bfloat16 g_kh[LSEQ * DMODEL];
__device__ __align__(16) __nv_bfloat16 g_kl[LSEQ * DMODEL];
__device__ __align__(16) __nv_bfloat16 g_vh[LSEQ * DMODEL];
__device__ __align__(16) __nv_bfloat16 g_vl[LSEQ * DMODEL];
__device__ __align__(16) __nv_bfloat16 g_ahi[LSEQ * DMODEL];
__device__ __align__(16) __nv_bfloat16 g_alo[LSEQ * DMODEL];

// ---------------------------------------------------------------------------
// Base-ISA tensor-core + async-copy helpers
// ---------------------------------------------------------------------------
__device__ __forceinline__ uint32_t smem_u32(const void* p) {
    uint32_t a;
    asm("{ .reg .u64 t; cvta.to.shared.u64 t, %1; cvt.u32.u64 %0, t; }" : "=r"(a) : "l"(p));
    return a;
}
__device__ __forceinline__ void ldsm_x4(uint32_t* r, uint32_t addr) {
    asm volatile("ldmatrix.sync.aligned.m8n8.x4.shared.b16 {%0,%1,%2,%3}, [%4];"
                 : "=r"(r[0]), "=r"(r[1]), "=r"(r[2]), "=r"(r[3]) : "r"(addr));
}
__device__ __forceinline__ void ldsm_x4_t(uint32_t* r, uint32_t addr) {
    asm volatile("ldmatrix.sync.aligned.m8n8.x4.trans.shared.b16 {%0,%1,%2,%3}, [%4];"
                 : "=r"(r[0]), "=r"(r[1]), "=r"(r[2]), "=r"(r[3]) : "r"(addr));
}
__device__ __forceinline__ void mma16816(float* c, const uint32_t* a, const uint32_t* b) {
    asm volatile(
        "mma.sync.aligned.m16n8k16.row.col.f32.bf16.bf16.f32 "
        "{%0,%1,%2,%3}, {%4,%5,%6,%7}, {%8,%9}, {%0,%1,%2,%3};"
        : "+f"(c[0]), "+f"(c[1]), "+f"(c[2]), "+f"(c[3])
        : "r"(a[0]), "r"(a[1]), "r"(a[2]), "r"(a[3]), "r"(b[0]), "r"(b[1]));
}
__device__ __forceinline__ void cp16(uint32_t dst, const void* src) {
    asm volatile("cp.async.cg.shared.global [%0], [%1], 16;" :: "r"(dst), "l"(src));
}
#define CP_COMMIT() asm volatile("cp.async.commit_group;" ::: "memory")
#define CP_WAIT0()  asm volatile("cp.async.wait_group 0;" ::: "memory")
#define CP_WAIT1()  asm volatile("cp.async.wait_group 1;" ::: "memory")

__device__ __forceinline__ float ex2(float x) {
    float y;
    asm("ex2.approx.f32 %0, %1;" : "=f"(y) : "f"(x));
    return y;
}

// ---------------------------------------------------------------------------
// bf16 split helpers
// ---------------------------------------------------------------------------
__device__ __forceinline__ void split_bf16(float x, __nv_bfloat16& h, __nv_bfloat16& l) {
    h = __float2bfloat16(x);
    l = __float2bfloat16(x - __bfloat162float(h));
}
__device__ __forceinline__ void pack_pair(float a, float b, uint32_t& hi, uint32_t& lo) {
    __nv_bfloat162 h = __float22bfloat162_rn(make_float2(a, b));
    float ra = a - __bfloat162float(h.x);
    float rb = b - __bfloat162float(h.y);
    __nv_bfloat162 l = __float22bfloat162_rn(make_float2(ra, rb));
    hi = *reinterpret_cast<uint32_t*>(&h);
    lo = *reinterpret_cast<uint32_t*>(&l);
}

// ---------------------------------------------------------------------------
// Merged conversion kernel: z<3 = activation split; z>=3 = weight transpose+split
// ---------------------------------------------------------------------------
__global__ void conv_all_kernel(const float* __restrict__ q, const float* __restrict__ k,
                                const float* __restrict__ v,
                                const float* __restrict__ wq, const float* __restrict__ wk,
                                const float* __restrict__ wv, const float* __restrict__ wo) {
    const int z = blockIdx.z;
    if (z < 3) {
        const float* src = (z == 0) ? q : (z == 1) ? k : v;
        __nv_bfloat16* hi = g_xhi[z];
        __nv_bfloat16* lo = g_xlo[z];
        int i = (blockIdx.x * 256 + threadIdx.x) * 4;
        float4 xv = *(const float4*)(src + i);
        union { __nv_bfloat16 b[4]; uint2 u; } H, L;
        split_bf16(xv.x, H.b[0], L.b[0]);
        split_bf16(xv.y, H.b[1], L.b[1]);
        split_bf16(xv.z, H.b[2], L.b[2]);
        split_bf16(xv.w, H.b[3], L.b[3]);
        *(uint2*)(hi + i) = H.u;
        *(uint2*)(lo + i) = L.u;
    } else {
        if (blockIdx.x >= 1024) return;   // weight side needs only 32x32 = 1024 blocks
        __shared__ float tile[32][33];
        const int zw = z - 3;
        const float* W = (zw == 0) ? wq : (zw == 1) ? wk : (zw == 2) ? wv : wo;
        __nv_bfloat16* Thi = g_whi[zw];
        __nv_bfloat16* Tlo = g_wlo[zw];
        const int n0 = (blockIdx.x & 31) * 32;
        const int k0 = (blockIdx.x >> 5) * 32;
        const int tx = threadIdx.x & 31;
        const int ty = threadIdx.x >> 5;   // 0..7
#pragma unroll
        for (int i = 0; i < 4; i++)
            tile[ty + i * 8][tx] = W[(size_t)(k0 + ty + i * 8) * DMODEL + n0 + tx];
        __syncthreads();
#pragma unroll
        for (int i = 0; i < 4; i++) {
            float val = tile[tx][ty + i * 8];
            __nv_bfloat16 h, l;
            split_bf16(val, h, l);
            size_t o = (size_t)(n0 + ty + i * 8) * DMODEL + k0 + tx;
            Thi[o] = h;
            Tlo[o] = l;
        }
    }
}

// ---------------------------------------------------------------------------
// HMMA GEMM (R10 shape, measured best): 3-stage cp.async ring, CTA 128x128,
// BK=64, 256 threads, 3-pass bf16 split.
// ---------------------------------------------------------------------------
#define GSTRIDE 144                     // bytes per smem row: 64 bf16 + 8 pad
#define GTILE   (128 * GSTRIDE)         // 18432 B
#define OF_AH   0
#define OF_AL   (1 * GTILE)
#define OF_BH   (2 * GTILE)
#define OF_BL   (3 * GTILE)
#define GBUF    (4 * GTILE)             // 73728 B per stage
#define GEMM_SMEM (3 * GBUF)            // 221184 B

extern __shared__ char smraw[];

__device__ __forceinline__ void issue_tile(uint32_t dst, const __nv_bfloat16* __restrict__ src,
                                           int row0, int k0, int tid) {
#pragma unroll
    for (int i = 0; i < 4; i++) {
        int idx = tid + i * 256;
        int row = idx >> 3;
        int c16 = idx & 7;
        cp16(dst + row * GSTRIDE + c16 * 16,
             src + (size_t)(row0 + row) * DMODEL + k0 + c16 * 8);
    }
}

__device__ __forceinline__ void issue_stage(uint32_t buf,
                                            const __nv_bfloat16* Ah, const __nv_bfloat16* Al,
                                            const __nv_bfloat16* Bh, const __nv_bfloat16* Bl,
                                            int bm, int bn, int k0, int tid) {
    issue_tile(buf + OF_AH, Ah, bm, k0, tid);
    issue_tile(buf + OF_AL, Al, bm, k0, tid);
    issue_tile(buf + OF_BH, Bh, bn, k0, tid);
    issue_tile(buf + OF_BL, Bl, bn, k0, tid);
    CP_COMMIT();
}

template <int SPLIT>
__device__ __forceinline__ void gemm_mma_body(
    const __nv_bfloat16* __restrict__ Ah, const __nv_bfloat16* __restrict__ Al,
    const __nv_bfloat16* __restrict__ Bh, const __nv_bfloat16* __restrict__ Bl,
    const float* __restrict__ bias, float oscale,
    float* __restrict__ C, __nv_bfloat16* __restrict__ Chi, __nv_bfloat16* __restrict__ Clo)
{
    const uint32_t smb = smem_u32(smraw);
    const int tid  = threadIdx.x;
    const int lane = tid & 31;
    const int wid  = tid >> 5;
    const int wm   = wid >> 2;
    const int wn   = wid & 3;
    const int bm   = blockIdx.y * 128;
    const int bn   = blockIdx.x * 128;
    const int NCH  = DMODEL / 64;       // 16

    float acc[4][4][4];
#pragma unroll
    for (int mi = 0; mi < 4; mi++)
#pragma unroll
        for (int ni = 0; ni < 4; ni++)
#pragma unroll
            for (int c = 0; c < 4; c++) acc[mi][ni][c] = 0.0f;

    const uint32_t aBase = (uint32_t)(wm * 64 + (lane & 15)) * GSTRIDE + ((lane >> 4) << 4);
    const uint32_t bBase = (uint32_t)(wn * 32 + (lane & 7) + ((lane >> 4) << 3)) * GSTRIDE
                         + (((lane >> 3) & 1) << 4);

    issue_stage(smb + 0 * GBUF, Ah, Al, Bh, Bl, bm, bn, 0, tid);
    issue_stage(smb + 1 * GBUF, Ah, Al, Bh, Bl, bm, bn, 64, tid);

    int cbi = 0;
    for (int chunk = 0; chunk < NCH; chunk++) {
        if (chunk < NCH - 1) CP_WAIT1(); else CP_WAIT0();
        __syncthreads();
        if (chunk + 2 < NCH) {
            int nbi = cbi + 2; if (nbi >= 3) nbi -= 3;
            issue_stage(smb + nbi * GBUF, Ah, Al, Bh, Bl, bm, bn, (chunk + 2) * 64, tid);
        }
        const uint32_t cb = smb + cbi * GBUF;

#pragma unroll
        for (int kk = 0; kk < 4; kk++) {
            const uint32_t kOff = kk * 32;
            uint32_t ah[4][4], al[4][4], bh[2][4], bl[2][4];
#pragma unroll
            for (int mi = 0; mi < 4; mi++) {
                ldsm_x4(ah[mi], cb + OF_AH + aBase + mi * (16 * GSTRIDE) + kOff);
                ldsm_x4(al[mi], cb + OF_AL + aBase + mi * (16 * GSTRIDE) + kOff);
            }
#pragma unroll
            for (int nj = 0; nj < 2; nj++) {
                ldsm_x4(bh[nj], cb + OF_BH + bBase + nj * (16 * GSTRIDE) + kOff);
                ldsm_x4(bl[nj], cb + OF_BL + bBase + nj * (16 * GSTRIDE) + kOff);
            }
#pragma unroll
            for (int mi = 0; mi < 4; mi++)
#pragma unroll
                for (int ni = 0; ni < 4; ni++)
                    mma16816(acc[mi][ni], ah[mi], &bh[ni >> 1][(ni & 1) * 2]);
#pragma unroll
            for (int mi = 0; mi < 4; mi++)
#pragma unroll
                for (int ni = 0; ni < 4; ni++)
                    mma16816(acc[mi][ni], ah[mi], &bl[ni >> 1][(ni & 1) * 2]);
#pragma unroll
            for (int mi = 0; mi < 4; mi++)
#pragma unroll
                for (int ni = 0; ni < 4; ni++)
                    mma16816(acc[mi][ni], al[mi], &bh[ni >> 1][(ni & 1) * 2]);
        }
        if (++cbi >= 3) cbi -= 3;
    }

    const int g = lane >> 2;
    const int t = lane & 3;
#pragma unroll
    for (int mi = 0; mi < 4; mi++) {
        const int row = bm + wm * 64 + mi * 16 + g;
#pragma unroll
        for (int ni = 0; ni < 4; ni++) {
            const int col = bn + wn * 32 + ni * 8 + t * 2;
            const float b0 = bias[col], b1 = bias[col + 1];
            float v0 = acc[mi][ni][0] + b0, v1 = acc[mi][ni][1] + b1;
            float v2 = acc[mi][ni][2] + b0, v3 = acc[mi][ni][3] + b1;
            if (SPLIT) {
                v0 *= oscale; v1 *= oscale; v2 *= oscale; v3 *= oscale;
                uint32_t h0, l0, h1, l1;
                pack_pair(v0, v1, h0, l0);
                pack_pair(v2, v3, h1, l1);
                const size_t o0 = (size_t)row * DMODEL + col;
                const size_t o1 = (size_t)(row + 8) * DMODEL + col;
                *(uint32_t*)(Chi + o0) = h0;
                *(uint32_t*)(Clo + o0) = l0;
                *(uint32_t*)(Chi + o1) = h1;
                *(uint32_t*)(Clo + o1) = l1;
            } else {
                *(float2*)(C + (size_t)row * DMODEL + col)       = make_float2(v0, v1);
                *(float2*)(C + (size_t)(row + 8) * DMODEL + col) = make_float2(v2, v3);
            }
        }
    }
}

// fold softmax scale AND log2(e) into Q so attention can use raw ex2
#define QSCALE (0.125f * 1.44269504088896340736f)

__global__ __launch_bounds__(256) void qkv_mma_kernel(
    const float* __restrict__ bq, const float* __restrict__ bk, const float* __restrict__ bv)
{
    int z = blockIdx.z;
    const float* bias = (z == 0) ? bq : (z == 1) ? bk : bv;
    __nv_bfloat16* Chi = (z == 0) ? g_qh : (z == 1) ? g_kh : g_vh;
    __nv_bfloat16* Clo = (z == 0) ? g_ql : (z == 1) ? g_kl : g_vl;
    const float sc = (z == 0) ? QSCALE : 1.0f;
    gemm_mma_body<1>(g_xhi[z], g_xlo[z], g_whi[z], g_wlo[z], bias, sc, nullptr, Chi, Clo);
}

__global__ __launch_bounds__(256) void out_mma_kernel(
    const float* __restrict__ bo, float* __restrict__ out)
{
    gemm_mma_body<0>(g_ahi, g_alo, g_whi[3], g_wlo[3], bo, 1.0f, out, nullptr, nullptr);
}

// ---------------------------------------------------------------------------
// HMMA flash attention (R10-exact, best measured): shift-free log2-domain
// softmax, QK/PV pipelined by jp-blocks, double-buffered K/V, q-tile 128.
// ---------------------------------------------------------------------------
#define AT_QH 0
#define AT_QL (1 * GTILE)
#define AT_KV (2 * GTILE)
#define KV_KH 0
#define KV_KL (1 * GTILE)
#define KV_VH (2 * GTILE)
#define KV_VL (3 * GTILE)
#define KVBUF (4 * GTILE)
#define ATTN_SMEM (AT_KV + 2 * KVBUF)

__device__ __forceinline__ void issue_kv(uint32_t base, int kt0, int h, int tid) {
#pragma unroll
    for (int i = 0; i < 4; i++) {
        int idx = tid + i * 256;
        int row = idx >> 3;
        int c16 = idx & 7;
        const uint32_t so = row * GSTRIDE + c16 * 16;
        const size_t go = (size_t)(kt0 + row) * DMODEL + h * HDIM + c16 * 8;
        cp16(base + KV_KH + so, g_kh + go);
        cp16(base + KV_KL + so, g_kl + go);
        cp16(base + KV_VH + so, g_vh + go);
        cp16(base + KV_VL + so, g_vl + go);
    }
}

__global__ __launch_bounds__(256, 1) void attn_mma_kernel()
{
    char* sm = smraw;
    const uint32_t smb = smem_u32(sm);
    const int tid  = threadIdx.x;
    const int lane = tid & 31;
    const int w    = tid >> 5;
    const int g    = lane >> 2;
    const int t    = lane & 3;
    const int h    = blockIdx.y;
    const int q0   = blockIdx.x * 128;

    issue_kv(smb + AT_KV, 0, h, tid);
    CP_COMMIT();

#pragma unroll
    for (int i = 0; i < 4; i++) {
        int idx = tid + i * 256;
        int row = idx >> 3;
        int c16 = idx & 7;
        const uint32_t so = row * GSTRIDE + c16 * 16;
        const size_t go = (size_t)(q0 + row) * DMODEL + h * HDIM + c16 * 8;
        *(uint4*)(sm + AT_QH + so) = *(const uint4*)(g_qh + go);
        *(uint4*)(sm + AT_QL + so) = *(const uint4*)(g_ql + go);
    }

    const uint32_t aOff = (uint32_t)(w * 16 + (lane & 15)) * GSTRIDE + ((lane >> 4) << 4);
    const uint32_t bOff = (uint32_t)((lane & 7) + ((lane >> 4) << 3)) * GSTRIDE
                        + (((lane >> 3) & 1) << 4);
    const uint32_t vOff = (uint32_t)((lane & 7) + (((lane >> 3) & 1) << 3)) * GSTRIDE
                        + ((lane >> 4) << 4);

    __syncthreads();

    uint32_t qfh[4][4], qfl[4][4];
#pragma unroll
    for (int ks = 0; ks < 4; ks++) {
        ldsm_x4(qfh[ks], smb + AT_QH + aOff + ks * 32);
        ldsm_x4(qfl[ks], smb + AT_QL + aOff + ks * 32);
    }

    float o[8][4];
#pragma unroll
    for (int i = 0; i < 8; i++)
#pragma unroll
        for (int c = 0; c < 4; c++) o[i][c] = 0.0f;
    float l0 = 0.0f, l1 = 0.0f;

    for (int it = 0; it < LSEQ / 128; it++) {
        const uint32_t kb = smb + AT_KV + (it & 1) * KVBUF;
        if (it < LSEQ / 128 - 1) {
            issue_kv(smb + AT_KV + ((it + 1) & 1) * KVBUF, (it + 1) * 128, h, tid);
            CP_COMMIT();
            CP_WAIT1();
        } else {
            CP_WAIT0();
        }
        __syncthreads();

        float s[16][4];
#pragma unroll
        for (int j = 0; j < 16; j++)
#pragma unroll
            for (int c = 0; c < 4; c++) s[j][c] = 0.0f;

        // ---- pipelined: QK(0); for jp: { QK(jp+1); exp+PV(jp) } ----
#pragma unroll
        for (int ph_i = 0; ph_i <= 4; ph_i++) {
            if (ph_i < 4) {
                const int jn = ph_i;
#pragma unroll
                for (int ks = 0; ks < 4; ks++) {
                    const uint32_t kOff = ks * 32;
                    uint32_t kha[4], kla[4], khb[4], klb[4];
                    const uint32_t ka  = bOff + (2 * jn) * (16 * GSTRIDE) + kOff;
                    const uint32_t ka2 = bOff + (2 * jn + 1) * (16 * GSTRIDE) + kOff;
                    ldsm_x4(kha, kb + KV_KH + ka);
                    ldsm_x4(kla, kb + KV_KL + ka);
                    ldsm_x4(khb, kb + KV_KH + ka2);
                    ldsm_x4(klb, kb + KV_KL + ka2);
                    float* s0 = s[4 * jn + 0];
                    float* s1 = s[4 * jn + 1];
                    float* s2 = s[4 * jn + 2];
                    float* s3 = s[4 * jn + 3];
                    mma16816(s0, qfh[ks], &kha[0]);
                    mma16816(s1, qfh[ks], &kha[2]);
                    mma16816(s2, qfh[ks], &khb[0]);
                    mma16816(s3, qfh[ks], &khb[2]);
                    mma16816(s0, qfh[ks], &kla[0]);
                    mma16816(s1, qfh[ks], &kla[2]);
                    mma16816(s2, qfh[ks], &klb[0]);
                    mma16816(s3, qfh[ks], &klb[2]);
                    mma16816(s0, qfl[ks], &kha[0]);
                    mma16816(s1, qfl[ks], &kha[2]);
                    mma16816(s2, qfl[ks], &khb[0]);
                    mma16816(s3, qfl[ks], &khb[2]);
                }
            }
            if (ph_i >= 1) {
                const int jp = ph_i - 1;
                uint32_t ph[2][4], pl[2][4];
#pragma unroll
                for (int u = 0; u < 2; u++) {
                    const int j0 = 4 * jp + 2 * u;
                    float p00 = ex2(s[j0][0]),     p01 = ex2(s[j0][1]);
                    float p02 = ex2(s[j0][2]),     p03 = ex2(s[j0][3]);
                    float p10 = ex2(s[j0 + 1][0]), p11 = ex2(s[j0 + 1][1]);
                    float p12 = ex2(s[j0 + 1][2]), p13 = ex2(s[j0 + 1][3]);
                    l0 += (p00 + p01) + (p10 + p11);
                    l1 += (p02 + p03) + (p12 + p13);
                    pack_pair(p00, p01, ph[u][0], pl[u][0]);
                    pack_pair(p02, p03, ph[u][1], pl[u][1]);
                    pack_pair(p10, p11, ph[u][2], pl[u][2]);
                    pack_pair(p12, p13, ph[u][3], pl[u][3]);
                }
#pragma unroll
                for (int u = 0; u < 2; u++) {
                    const int kt = 2 * jp + u;
#pragma unroll
                    for (int dpp = 0; dpp < 2; dpp++) {
                        uint32_t vha[4], vla[4], vhb[4], vlb[4];
                        const uint32_t va = vOff + kt * (16 * GSTRIDE) + (2 * dpp) * 32;
                        const uint32_t vb = vOff + kt * (16 * GSTRIDE) + (2 * dpp + 1) * 32;
                        ldsm_x4_t(vha, kb + KV_VH + va);
                        ldsm_x4_t(vla, kb + KV_VL + va);
                        ldsm_x4_t(vhb, kb + KV_VH + vb);
                        ldsm_x4_t(vlb, kb + KV_VL + vb);
                        float* o0 = o[4 * dpp + 0];
                        float* o1 = o[4 * dpp + 1];
                        float* o2 = o[4 * dpp + 2];
                        float* o3 = o[4 * dpp + 3];
                        mma16816(o0, ph[u], &vha[0]);
                        mma16816(o1, ph[u], &vha[2]);
                        mma16816(o2, ph[u], &vhb[0]);
                        mma16816(o3, ph[u], &vhb[2]);
                        mma16816(o0, pl[u], &vha[0]);
                        mma16816(o1, pl[u], &vha[2]);
                        mma16816(o2, pl[u], &vhb[0]);
                        mma16816(o3, pl[u], &vhb[2]);
                        mma16816(o0, ph[u], &vla[0]);
                        mma16816(o1, ph[u], &vla[2]);
                        mma16816(o2, ph[u], &vlb[0]);
                        mma16816(o3, ph[u], &vlb[2]);
                    }
                }
            }
        }
        __syncthreads();
    }

    // Final row-sum reduction (once) and normalize; write split bf16
    l0 += __shfl_xor_sync(0xffffffffu, l0, 1);
    l0 += __shfl_xor_sync(0xffffffffu, l0, 2);
    l1 += __shfl_xor_sync(0xffffffffu, l1, 1);
    l1 += __shfl_xor_sync(0xffffffffu, l1, 2);
    const float inv0 = 1.0f / l0;
    const float inv1 = 1.0f / l1;
    const int row = q0 + w * 16 + g;
#pragma unroll
    for (int dt = 0; dt < 8; dt++) {
        const int col = h * HDIM + dt * 8 + t * 2;
        uint32_t h0, l0u, h1, l1u;
        pack_pair(o[dt][0] * inv0, o[dt][1] * inv0, h0, l0u);
        pack_pair(o[dt][2] * inv1, o[dt][3] * inv1, h1, l1u);
        const size_t o0 = (size_t)row * DMODEL + col;
        const size_t o1 = (size_t)(row + 8) * DMODEL + col;
        *(uint32_t*)(g_ahi + o0) = h0;
        *(uint32_t*)(g_alo + o0) = l0u;
        *(uint32_t*)(g_ahi + o1) = h1;
        *(uint32_t*)(g_alo + o1) = l1u;
    }
}

// ---------------------------------------------------------------------------
extern "C" void kernel_launch(void* const* d_in, const int* in_sizes, int n_in,
                              void* d_out, int out_size)
{
    const float* q  = (const float*)d_in[0];
    const float* k  = (const float*)d_in[1];
    const float* v  = (const float*)d_in[2];
    const float* wq = (const float*)d_in[3];
    const float* bq = (const float*)d_in[4];
    const float* wk = (const float*)d_in[5];
    const float* bk = (const float*)d_in[6];
    const float* wv = (const float*)d_in[7];
    const float* bv = (const float*)d_in[8];
    const float* wo = (const float*)d_in[9];
    const float* bo = (const float*)d_in[10];
    float* out = (float*)d_out;

    (void)in_sizes; (void)n_in; (void)out_size;

    cudaFuncSetAttribute(qkv_mma_kernel, cudaFuncAttributeMaxDynamicSharedMemorySize, GEMM_SMEM);
    cudaFuncSetAttribute(out_mma_kernel, cudaFuncAttributeMaxDynamicSharedMemorySize, GEMM_SMEM);
    cudaFuncSetAttribute(attn_mma_kernel, cudaFuncAttributeMaxDynamicSharedMemorySize, ATTN_SMEM);

    // 1. All conversions in one launch (activations z=0..2, weights z=3..6)
    {
        dim3 grid(LSEQ * DMODEL / (256 * 4), 1, 7);
        conv_all_kernel<<<grid, 256>>>(q, k, v, wq, wk, wv, wo);
    }
    // 2. QKV projections (R10 GEMM: 256-thr, 3-stage ring)
    {
        dim3 grid(DMODEL / 128, LSEQ / 128, 3);
        qkv_mma_kernel<<<grid, 256, GEMM_SMEM>>>(bq, bk, bv);
    }
    // 3. Attention (R10: q-tile 128, double-buffered, pipelined)
    {
        dim3 grid(LSEQ / 128, NHEAD);
        attn_mma_kernel<<<grid, 256, ATTN_SMEM>>>();
    }
    // 4. Output projection (R10 GEMM)
    {
        dim3 grid(DMODEL / 128, LSEQ / 128);
        out_mma_kernel<<<grid, 256, GEMM_SMEM>>>(bo, out);
    }
}